// round 1
// baseline (speedup 1.0000x reference)
#include <cuda_runtime.h>
#include <math.h>

// Problem constants
#define Bb  4
#define Ss  2048
#define Dd  1024
#define Hh  16
#define HSs 64
#define MM  (Bb*Ss)   // 8192 rows

// ---------------------------------------------------------------------------
// Device scratch (no allocations allowed in kernel_launch)
// ---------------------------------------------------------------------------
__device__ float g_lnv[MM*Dd];
__device__ float g_lnk[MM*Dd];
__device__ float g_lnq[MM*Dd];
__device__ float g_qp [MM*Dd];   // projected Q, [B,S,D] with D = h*64+e
__device__ float g_kp [MM*Dd];
__device__ float g_vp [MM*Dd];
__device__ float g_attn[MM*Dd];  // concat-head attention output
__device__ float g_Wq2[Dd*Dd];   // [K,N] plain layout
__device__ float g_Wk2[Dd*Dd];
__device__ float g_Wv2[Dd*Dd];
__device__ float g_WpT[Dd*Dd];   // Wp transposed -> [K,N]

// ---------------------------------------------------------------------------
// Weight reorder: Wx[h,d,e] -> W2[d, h*64+e]; WpT[k,j] = Wp[j,k]
// ---------------------------------------------------------------------------
__global__ void reorder_kernel(const float* __restrict__ Wq,
                               const float* __restrict__ Wk,
                               const float* __restrict__ Wv,
                               const float* __restrict__ Wp) {
    int idx = blockIdx.x * 256 + threadIdx.x;   // 0 .. D*D-1
    int k = idx >> 10;
    int j = idx & 1023;
    int h = j >> 6;
    int e = j & 63;
    int src = h * (Dd * HSs) + k * HSs + e;
    g_Wq2[idx] = Wq[src];
    g_Wk2[idx] = Wk[src];
    g_Wv2[idx] = Wv[src];
    g_WpT[idx] = Wp[(size_t)j * Dd + k];
}

// ---------------------------------------------------------------------------
// Fused layernorm for v,k,q  (grid: (MM, 3), 256 threads, float4)
// ---------------------------------------------------------------------------
__global__ __launch_bounds__(256) void ln_kernel(const float* __restrict__ v,
                                                 const float* __restrict__ k,
                                                 const float* __restrict__ q,
                                                 const float* __restrict__ g,
                                                 const float* __restrict__ b) {
    int row   = blockIdx.x;
    int which = blockIdx.y;
    const float* x;
    float* y;
    if (which == 0)      { x = v; y = g_lnv; }
    else if (which == 1) { x = k; y = g_lnk; }
    else                 { x = q; y = g_lnq; }
    x += (size_t)row * Dd;
    y += (size_t)row * Dd;

    int t = threadIdx.x;
    float4 xv = ((const float4*)x)[t];
    float s1 = xv.x + xv.y + xv.z + xv.w;
    float s2 = xv.x*xv.x + xv.y*xv.y + xv.z*xv.z + xv.w*xv.w;
    #pragma unroll
    for (int off = 16; off; off >>= 1) {
        s1 += __shfl_xor_sync(0xffffffffu, s1, off);
        s2 += __shfl_xor_sync(0xffffffffu, s2, off);
    }
    __shared__ float w1[8], w2[8];
    __shared__ float smu, srs;
    int wid = t >> 5, lid = t & 31;
    if (lid == 0) { w1[wid] = s1; w2[wid] = s2; }
    __syncthreads();
    if (t == 0) {
        float t1 = 0.f, t2 = 0.f;
        #pragma unroll
        for (int i = 0; i < 8; i++) { t1 += w1[i]; t2 += w2[i]; }
        float mu  = t1 * (1.0f / Dd);
        float var = t2 * (1.0f / Dd) - mu * mu;
        smu = mu;
        srs = rsqrtf(var + 1e-5f);
    }
    __syncthreads();
    float mu = smu, rs = srs;
    float4 gv = ((const float4*)g)[t];
    float4 bv = ((const float4*)b)[t];
    float4 yv;
    yv.x = (xv.x - mu) * rs * gv.x + bv.x;
    yv.y = (xv.y - mu) * rs * gv.y + bv.y;
    yv.z = (xv.z - mu) * rs * gv.z + bv.z;
    yv.w = (xv.w - mu) * rs * gv.w + bv.w;
    ((float4*)y)[t] = yv;
}

// ---------------------------------------------------------------------------
// SGEMM: C[M,1024] = A[M,1024] * Bm[1024,1024] (+ bias)
// 128x128 tile, BK=16, 256 threads, 8x8 per thread
// grid: (8, M/128)
// ---------------------------------------------------------------------------
__global__ __launch_bounds__(256) void sgemm_kernel(const float* __restrict__ A,
                                                    const float* __restrict__ Bm,
                                                    float* __restrict__ C,
                                                    const float* __restrict__ bias) {
    __shared__ float As[16][128];
    __shared__ float Bs[16][128];
    int tid = threadIdx.x;
    int m0 = blockIdx.y * 128;
    int n0 = blockIdx.x * 128;
    int tr = tid >> 4;           // 0..15
    int tc = tid & 15;           // 0..15
    int ar = tid >> 2;           // 0..63
    int ac = (tid & 3) << 2;     // 0,4,8,12
    int bk = tid >> 5;           // 0..7
    int bj = (tid & 31) << 2;    // 0..124

    float acc[8][8];
    #pragma unroll
    for (int i = 0; i < 8; i++)
        #pragma unroll
        for (int j = 0; j < 8; j++) acc[i][j] = 0.f;

    for (int k0 = 0; k0 < Dd; k0 += 16) {
        float4 a0 = *(const float4*)(A + (size_t)(m0 + ar)      * Dd + k0 + ac);
        float4 a1 = *(const float4*)(A + (size_t)(m0 + ar + 64) * Dd + k0 + ac);
        As[ac + 0][ar]      = a0.x;
        As[ac + 1][ar]      = a0.y;
        As[ac + 2][ar]      = a0.z;
        As[ac + 3][ar]      = a0.w;
        As[ac + 0][ar + 64] = a1.x;
        As[ac + 1][ar + 64] = a1.y;
        As[ac + 2][ar + 64] = a1.z;
        As[ac + 3][ar + 64] = a1.w;
        *(float4*)&Bs[bk][bj]     = *(const float4*)(Bm + (size_t)(k0 + bk)     * Dd + n0 + bj);
        *(float4*)&Bs[bk + 8][bj] = *(const float4*)(Bm + (size_t)(k0 + bk + 8) * Dd + n0 + bj);
        __syncthreads();
        #pragma unroll
        for (int kk = 0; kk < 16; kk++) {
            float a[8], bb[8];
            *(float4*)&a[0]  = *(const float4*)&As[kk][tr * 8];
            *(float4*)&a[4]  = *(const float4*)&As[kk][tr * 8 + 4];
            *(float4*)&bb[0] = *(const float4*)&Bs[kk][tc * 8];
            *(float4*)&bb[4] = *(const float4*)&Bs[kk][tc * 8 + 4];
            #pragma unroll
            for (int i = 0; i < 8; i++)
                #pragma unroll
                for (int j = 0; j < 8; j++)
                    acc[i][j] += a[i] * bb[j];
        }
        __syncthreads();
    }

    float bv[8];
    #pragma unroll
    for (int j = 0; j < 8; j++) bv[j] = bias ? bias[n0 + tc * 8 + j] : 0.f;

    #pragma unroll
    for (int i = 0; i < 8; i++) {
        size_t off = (size_t)(m0 + tr * 8 + i) * Dd + n0 + tc * 8;
        float4 c0 = make_float4(acc[i][0] + bv[0], acc[i][1] + bv[1],
                                acc[i][2] + bv[2], acc[i][3] + bv[3]);
        float4 c1 = make_float4(acc[i][4] + bv[4], acc[i][5] + bv[5],
                                acc[i][6] + bv[6], acc[i][7] + bv[7]);
        *(float4*)(C + off)     = c0;
        *(float4*)(C + off + 4) = c1;
    }
}

// ---------------------------------------------------------------------------
// Flash attention, fp32, causal. BM=BN=64, 256 threads (16x16), 4x4 microtile.
// Q/K/V in [B,S,D] with head slice at column h*64; output to g_attn same layout.
// grid: (S/64, B*H), dynamic smem = 4 * 64*68 floats
// ---------------------------------------------------------------------------
#define ATT_PITCH 68
#define ATT_SMEM  (4 * 64 * ATT_PITCH * (int)sizeof(float))

__global__ __launch_bounds__(256) void attn_kernel() {
    extern __shared__ float sm[];
    float (*Qs)[ATT_PITCH]  = (float(*)[ATT_PITCH])(sm);
    float (*Kst)[ATT_PITCH] = (float(*)[ATT_PITCH])(sm + 64 * ATT_PITCH);      // K^T: [e][n]
    float (*Vs)[ATT_PITCH]  = (float(*)[ATT_PITCH])(sm + 2 * 64 * ATT_PITCH); // [n][e]
    float (*Ps)[ATT_PITCH]  = (float(*)[ATT_PITCH])(sm + 3 * 64 * ATT_PITCH); // [r][c]

    int qb = blockIdx.x;
    int bh = blockIdx.y;
    int b  = bh >> 4;
    int h  = bh & 15;
    size_t base = (size_t)b * Ss * Dd + (size_t)h * HSs;
    const float* Qp = g_qp + base;
    const float* Kp = g_kp + base;
    const float* Vp = g_vp + base;
    float* Op = g_attn + base;
    int q0 = qb * 64;

    int tid = threadIdx.x;
    int tr = tid >> 4, tc = tid & 15;
    int tr4 = tr * 4, tc4 = tc * 4;

    // Load Q tile once
    for (int idx = tid; idx < 64 * 16; idx += 256) {
        int r = idx >> 4, c = (idx & 15) << 2;
        *(float4*)&Qs[r][c] = *(const float4*)(Qp + (size_t)(q0 + r) * Dd + c);
    }

    float m[4], l[4], o[4][4];
    #pragma unroll
    for (int i = 0; i < 4; i++) {
        m[i] = -1e30f; l[i] = 0.f;
        #pragma unroll
        for (int j = 0; j < 4; j++) o[i][j] = 0.f;
    }

    const float SC = 0.03125f;  // 1/sqrt(1024)

    for (int kb = 0; kb <= qb; kb++) {
        int k0 = kb * 64;
        __syncthreads();  // prior PV reads of Vs/Ps complete
        for (int idx = tid; idx < 64 * 16; idx += 256) {
            int r = idx >> 4, c = (idx & 15) << 2;
            float4 kv = *(const float4*)(Kp + (size_t)(k0 + r) * Dd + c);
            Kst[c + 0][r] = kv.x;
            Kst[c + 1][r] = kv.y;
            Kst[c + 2][r] = kv.z;
            Kst[c + 3][r] = kv.w;
            *(float4*)&Vs[r][c] = *(const float4*)(Vp + (size_t)(k0 + r) * Dd + c);
        }
        __syncthreads();

        // S = Q K^T (4x4 per thread)
        float s[4][4];
        #pragma unroll
        for (int i = 0; i < 4; i++)
            #pragma unroll
            for (int j = 0; j < 4; j++) s[i][j] = 0.f;

        #pragma unroll
        for (int e = 0; e < 64; e += 4) {
            float4 k0v = *(const float4*)&Kst[e + 0][tc4];
            float4 k1v = *(const float4*)&Kst[e + 1][tc4];
            float4 k2v = *(const float4*)&Kst[e + 2][tc4];
            float4 k3v = *(const float4*)&Kst[e + 3][tc4];
            #pragma unroll
            for (int i = 0; i < 4; i++) {
                float4 qv = *(const float4*)&Qs[tr4 + i][e];
                s[i][0] += qv.x*k0v.x + qv.y*k1v.x + qv.z*k2v.x + qv.w*k3v.x;
                s[i][1] += qv.x*k0v.y + qv.y*k1v.y + qv.z*k2v.y + qv.w*k3v.y;
                s[i][2] += qv.x*k0v.z + qv.y*k1v.z + qv.z*k2v.z + qv.w*k3v.z;
                s[i][3] += qv.x*k0v.w + qv.y*k1v.w + qv.z*k2v.w + qv.w*k3v.w;
            }
        }

        // scale + causal mask (only diagonal block needs masking)
        if (kb == qb) {
            #pragma unroll
            for (int i = 0; i < 4; i++)
                #pragma unroll
                for (int j = 0; j < 4; j++) {
                    int kg = k0 + tc4 + j;
                    int qg = q0 + tr4 + i;
                    s[i][j] = (kg <= qg) ? s[i][j] * SC : -1e30f;
                }
        } else {
            #pragma unroll
            for (int i = 0; i < 4; i++)
                #pragma unroll
                for (int j = 0; j < 4; j++) s[i][j] *= SC;
        }

        // online softmax (row groups = 16 lanes sharing tr)
        #pragma unroll
        for (int i = 0; i < 4; i++) {
            float mx = fmaxf(fmaxf(s[i][0], s[i][1]), fmaxf(s[i][2], s[i][3]));
            mx = fmaxf(mx, __shfl_xor_sync(0xffffffffu, mx, 1));
            mx = fmaxf(mx, __shfl_xor_sync(0xffffffffu, mx, 2));
            mx = fmaxf(mx, __shfl_xor_sync(0xffffffffu, mx, 4));
            mx = fmaxf(mx, __shfl_xor_sync(0xffffffffu, mx, 8));
            float mn = fmaxf(m[i], mx);
            float al = __expf(m[i] - mn);
            float p0 = __expf(s[i][0] - mn);
            float p1 = __expf(s[i][1] - mn);
            float p2 = __expf(s[i][2] - mn);
            float p3 = __expf(s[i][3] - mn);
            float rs = p0 + p1 + p2 + p3;
            rs += __shfl_xor_sync(0xffffffffu, rs, 1);
            rs += __shfl_xor_sync(0xffffffffu, rs, 2);
            rs += __shfl_xor_sync(0xffffffffu, rs, 4);
            rs += __shfl_xor_sync(0xffffffffu, rs, 8);
            l[i] = l[i] * al + rs;
            m[i] = mn;
            o[i][0] *= al; o[i][1] *= al; o[i][2] *= al; o[i][3] *= al;
            float4 pv = make_float4(p0, p1, p2, p3);
            *(float4*)&Ps[tr4 + i][tc4] = pv;
        }
        __syncthreads();

        // O += P V
        #pragma unroll 8
        for (int kk = 0; kk < 64; kk++) {
            float4 vv = *(const float4*)&Vs[kk][tc4];
            #pragma unroll
            for (int i = 0; i < 4; i++) {
                float p = Ps[tr4 + i][kk];
                o[i][0] += p * vv.x;
                o[i][1] += p * vv.y;
                o[i][2] += p * vv.z;
                o[i][3] += p * vv.w;
            }
        }
    }

    #pragma unroll
    for (int i = 0; i < 4; i++) {
        float inv = 1.0f / l[i];
        float4 ov = make_float4(o[i][0] * inv, o[i][1] * inv,
                                o[i][2] * inv, o[i][3] * inv);
        *(float4*)(Op + (size_t)(q0 + tr4 + i) * Dd + tc4) = ov;
    }
}

// ---------------------------------------------------------------------------
// Host launch (graph-capturable: kernels only)
// ---------------------------------------------------------------------------
extern "C" void kernel_launch(void* const* d_in, const int* in_sizes, int n_in,
                              void* d_out, int out_size) {
    const float* v   = (const float*)d_in[0];
    const float* k   = (const float*)d_in[1];
    const float* q   = (const float*)d_in[2];
    // d_in[3] = mask (causal, implicit — ignored)
    const float* lng = (const float*)d_in[4];
    const float* lnb = (const float*)d_in[5];
    const float* Wq  = (const float*)d_in[6];
    const float* Wk  = (const float*)d_in[7];
    const float* Wv  = (const float*)d_in[8];
    const float* Wp  = (const float*)d_in[9];
    const float* bp  = (const float*)d_in[10];
    float* out = (float*)d_out;

    void *p_lnv, *p_lnk, *p_lnq, *p_qp, *p_kp, *p_vp, *p_attn;
    void *p_wq2, *p_wk2, *p_wv2, *p_wpt;
    cudaGetSymbolAddress(&p_lnv,  g_lnv);
    cudaGetSymbolAddress(&p_lnk,  g_lnk);
    cudaGetSymbolAddress(&p_lnq,  g_lnq);
    cudaGetSymbolAddress(&p_qp,   g_qp);
    cudaGetSymbolAddress(&p_kp,   g_kp);
    cudaGetSymbolAddress(&p_vp,   g_vp);
    cudaGetSymbolAddress(&p_attn, g_attn);
    cudaGetSymbolAddress(&p_wq2,  g_Wq2);
    cudaGetSymbolAddress(&p_wk2,  g_Wk2);
    cudaGetSymbolAddress(&p_wv2,  g_Wv2);
    cudaGetSymbolAddress(&p_wpt,  g_WpT);

    cudaFuncSetAttribute(attn_kernel,
                         cudaFuncAttributeMaxDynamicSharedMemorySize, ATT_SMEM);

    reorder_kernel<<<(Dd * Dd) / 256, 256>>>(Wq, Wk, Wv, Wp);
    ln_kernel<<<dim3(MM, 3), 256>>>(v, k, q, lng, lnb);
    sgemm_kernel<<<dim3(8, MM / 128), 256>>>((const float*)p_lnq, (const float*)p_wq2,
                                             (float*)p_qp, nullptr);
    sgemm_kernel<<<dim3(8, MM / 128), 256>>>((const float*)p_lnk, (const float*)p_wk2,
                                             (float*)p_kp, nullptr);
    sgemm_kernel<<<dim3(8, MM / 128), 256>>>((const float*)p_lnv, (const float*)p_wv2,
                                             (float*)p_vp, nullptr);
    attn_kernel<<<dim3(Ss / 64, Bb * Hh), 256, ATT_SMEM>>>();
    sgemm_kernel<<<dim3(8, MM / 128), 256>>>((const float*)p_attn, (const float*)p_wpt,
                                             out, bp);
}

// round 5
// speedup vs baseline: 1.4938x; 1.4938x over previous
#include <cuda_runtime.h>
#include <cuda_bf16.h>
#include <cstdint>
#include <math.h>

// Problem constants
#define Bb  4
#define Ss  2048
#define Dd  1024
#define Hh  16
#define HSs 64
#define MM  (Bb*Ss)   // 8192 rows

// ---------------------------------------------------------------------------
// PTX helpers (baseline PTX only — harness emits compute_103, no 'a' features)
// ---------------------------------------------------------------------------
__device__ __forceinline__ uint32_t smem_u32(const void* p) {
    uint32_t a;
    asm("{ .reg .u64 t; cvta.to.shared.u64 t, %1; cvt.u32.u64 %0, t; }"
        : "=r"(a) : "l"(p));
    return a;
}

#define CP_ASYNC16(smem_addr, gptr) \
    asm volatile("cp.async.cg.shared.global [%0], [%1], 16;" \
                 :: "r"((uint32_t)(smem_addr)), "l"(gptr) : "memory")
#define CP_COMMIT() asm volatile("cp.async.commit_group;" ::: "memory")
#define CP_WAIT(n)  asm volatile("cp.async.wait_group %0;" :: "n"(n) : "memory")

__device__ __forceinline__ void ldsm4(uint32_t r[4], uint32_t addr) {
    asm volatile("ldmatrix.sync.aligned.m8n8.x4.shared.b16 {%0,%1,%2,%3}, [%4];"
                 : "=r"(r[0]), "=r"(r[1]), "=r"(r[2]), "=r"(r[3]) : "r"(addr));
}

__device__ __forceinline__ void mma16816(float c[4], const uint32_t a[4],
                                         uint32_t b0, uint32_t b1) {
    asm volatile(
        "mma.sync.aligned.m16n8k16.row.col.f32.bf16.bf16.f32 "
        "{%0,%1,%2,%3}, {%4,%5,%6,%7}, {%8,%9}, {%0,%1,%2,%3};"
        : "+f"(c[0]), "+f"(c[1]), "+f"(c[2]), "+f"(c[3])
        : "r"(a[0]), "r"(a[1]), "r"(a[2]), "r"(a[3]), "r"(b0), "r"(b1));
}

// ---------------------------------------------------------------------------
// Device scratch
// ---------------------------------------------------------------------------
__device__ __nv_bfloat16 g_lnvhi[MM*Dd];
__device__ __nv_bfloat16 g_lnvlo[MM*Dd];
__device__ __nv_bfloat16 g_lnkhi[MM*Dd];
__device__ __nv_bfloat16 g_lnklo[MM*Dd];
__device__ __nv_bfloat16 g_lnqhi[MM*Dd];
__device__ __nv_bfloat16 g_lnqlo[MM*Dd];
__device__ float g_qp[MM*Dd];
__device__ float g_kp[MM*Dd];
__device__ float g_vp[MM*Dd];
__device__ __nv_bfloat16 g_attnhi[MM*Dd];
__device__ __nv_bfloat16 g_attnlo[MM*Dd];
__device__ __nv_bfloat16 g_Wqhi[Dd*Dd];
__device__ __nv_bfloat16 g_Wqlo[Dd*Dd];
__device__ __nv_bfloat16 g_Wkhi[Dd*Dd];
__device__ __nv_bfloat16 g_Wklo[Dd*Dd];
__device__ __nv_bfloat16 g_Wvhi[Dd*Dd];
__device__ __nv_bfloat16 g_Wvlo[Dd*Dd];
__device__ __nv_bfloat16 g_Wphi[Dd*Dd];
__device__ __nv_bfloat16 g_Wplo[Dd*Dd];

__device__ __forceinline__ void bf_split(float x, __nv_bfloat16& h, __nv_bfloat16& l) {
    h = __float2bfloat16(x);
    l = __float2bfloat16(x - __bfloat162float(h));
}

// ---------------------------------------------------------------------------
// Weight reorder to [N,K] (K contiguous) + bf16 hi/lo split.
// Wx[h,d,e] -> W[n=h*64+e][k=d]; Wp[j,k] already [N=j][K=k].
// ---------------------------------------------------------------------------
__global__ void reorder_kernel(const float* __restrict__ Wq,
                               const float* __restrict__ Wk,
                               const float* __restrict__ Wv,
                               const float* __restrict__ Wp) {
    int idx = blockIdx.x * 256 + threadIdx.x;   // n*1024 + k
    int n = idx >> 10;
    int k = idx & 1023;
    int h = n >> 6;
    int e = n & 63;
    int src = h * (Dd * HSs) + k * HSs + e;
    __nv_bfloat16 hh, ll;
    bf_split(Wq[src], hh, ll); g_Wqhi[idx] = hh; g_Wqlo[idx] = ll;
    bf_split(Wk[src], hh, ll); g_Wkhi[idx] = hh; g_Wklo[idx] = ll;
    bf_split(Wv[src], hh, ll); g_Wvhi[idx] = hh; g_Wvlo[idx] = ll;
    bf_split(Wp[idx], hh, ll); g_Wphi[idx] = hh; g_Wplo[idx] = ll;
}

// ---------------------------------------------------------------------------
// Fused layernorm for v,k,q  (grid: (MM, 3), 256 threads) + bf16 hi/lo split
// ---------------------------------------------------------------------------
__global__ __launch_bounds__(256) void ln_kernel(const float* __restrict__ v,
                                                 const float* __restrict__ k,
                                                 const float* __restrict__ q,
                                                 const float* __restrict__ g,
                                                 const float* __restrict__ b) {
    int row   = blockIdx.x;
    int which = blockIdx.y;
    const float* x;
    __nv_bfloat16 *yh, *yl;
    if (which == 0)      { x = v; yh = g_lnvhi; yl = g_lnvlo; }
    else if (which == 1) { x = k; yh = g_lnkhi; yl = g_lnklo; }
    else                 { x = q; yh = g_lnqhi; yl = g_lnqlo; }
    x  += (size_t)row * Dd;
    yh += (size_t)row * Dd;
    yl += (size_t)row * Dd;

    int t = threadIdx.x;
    float4 xv = ((const float4*)x)[t];
    float s1 = xv.x + xv.y + xv.z + xv.w;
    float s2 = xv.x*xv.x + xv.y*xv.y + xv.z*xv.z + xv.w*xv.w;
    #pragma unroll
    for (int off = 16; off; off >>= 1) {
        s1 += __shfl_xor_sync(0xffffffffu, s1, off);
        s2 += __shfl_xor_sync(0xffffffffu, s2, off);
    }
    __shared__ float w1[8], w2[8];
    __shared__ float smu, srs;
    int wid = t >> 5, lid = t & 31;
    if (lid == 0) { w1[wid] = s1; w2[wid] = s2; }
    __syncthreads();
    if (t == 0) {
        float t1 = 0.f, t2 = 0.f;
        #pragma unroll
        for (int i = 0; i < 8; i++) { t1 += w1[i]; t2 += w2[i]; }
        float mu  = t1 * (1.0f / Dd);
        float var = t2 * (1.0f / Dd) - mu * mu;
        smu = mu;
        srs = rsqrtf(var + 1e-5f);
    }
    __syncthreads();
    float mu = smu, rs = srs;
    float4 gv = ((const float4*)g)[t];
    float4 bv = ((const float4*)b)[t];
    float y0 = (xv.x - mu) * rs * gv.x + bv.x;
    float y1 = (xv.y - mu) * rs * gv.y + bv.y;
    float y2 = (xv.z - mu) * rs * gv.z + bv.z;
    float y3 = (xv.w - mu) * rs * gv.w + bv.w;
    __nv_bfloat16 h0, l0, h1, l1, h2, l2, h3, l3;
    bf_split(y0, h0, l0); bf_split(y1, h1, l1);
    bf_split(y2, h2, l2); bf_split(y3, h3, l3);
    __nv_bfloat162* yh2 = (__nv_bfloat162*)yh;
    __nv_bfloat162* yl2 = (__nv_bfloat162*)yl;
    yh2[2*t]   = __nv_bfloat162{h0, h1};
    yh2[2*t+1] = __nv_bfloat162{h2, h3};
    yl2[2*t]   = __nv_bfloat162{l0, l1};
    yl2[2*t+1] = __nv_bfloat162{l2, l3};
}

// ---------------------------------------------------------------------------
// bf16x3 mma.sync GEMM: C[M,1024] = (Ahi+Alo) x (Bhi+Blo)^T (+bias), fp32 C.
// A rows [M,K] K-major; B rows [N,K] K-major (TN, natural mma layout).
// CTA tile 128x128, BK=32, 8 warps (2x4), warp tile 64x32, 2-stage cp.async.
// grid: (8, M/128), 256 threads.
// Smem stage: AH|AL|BH|BL each 128 rows x 64B, swizzle chunk^((row>>1)&3).
// ---------------------------------------------------------------------------
#define GB_STAGE 32768
#define GB_SMEM  (2 * GB_STAGE)

__device__ __forceinline__ void gb_load(const __nv_bfloat16* Ahi,
                                        const __nv_bfloat16* Alo,
                                        const __nv_bfloat16* Bhi,
                                        const __nv_bfloat16* Blo,
                                        int m0, int n0, int k0,
                                        uint32_t stage_base, int tid) {
    #pragma unroll
    for (int i = 0; i < 8; i++) {
        int gid = tid + i * 256;          // 0..2047
        int arr = gid >> 9;               // 0:AH 1:AL 2:BH 3:BL
        int idx = gid & 511;
        int row = idx >> 2;               // 0..127
        int c   = idx & 3;                // 16B chunk in 64B row
        uint32_t dst = stage_base + (uint32_t)arr * 8192u
                     + (uint32_t)row * 64u + (uint32_t)((c ^ ((row >> 1) & 3)) << 4);
        const __nv_bfloat16* p = (arr & 2) ? ((arr & 1) ? Blo : Bhi)
                                           : ((arr & 1) ? Alo : Ahi);
        int g0 = (arr & 2) ? n0 : m0;
        CP_ASYNC16(dst, p + (size_t)(g0 + row) * Dd + k0 + c * 8);
    }
    CP_COMMIT();
}

__global__ __launch_bounds__(256, 1) void gemm_bf3_kernel(
        const __nv_bfloat16* __restrict__ Ahi,
        const __nv_bfloat16* __restrict__ Alo,
        const __nv_bfloat16* __restrict__ Bhi,
        const __nv_bfloat16* __restrict__ Blo,
        float* __restrict__ C,
        const float* __restrict__ bias) {
    extern __shared__ char smem[];
    uint32_t sb = smem_u32(smem);

    int tid  = threadIdx.x;
    int wid  = tid >> 5;
    int lane = tid & 31;
    int m0 = blockIdx.y * 128;
    int n0 = blockIdx.x * 128;
    int wm = wid & 1;        // 0..1  -> 64-row half
    int wn = wid >> 1;       // 0..3  -> 32-col quarter

    float acc[4][4][4];
    #pragma unroll
    for (int i = 0; i < 4; i++)
        #pragma unroll
        for (int j = 0; j < 4; j++)
            #pragma unroll
            for (int r = 0; r < 4; r++) acc[i][j][r] = 0.f;

    gb_load(Ahi, Alo, Bhi, Blo, m0, n0, 0, sb, tid);

    int ti = lane >> 3, lr = lane & 7;

    const int NC = Dd / 32;   // 32 chunks
    for (int c = 0; c < NC; c++) {
        uint32_t sBase = sb + (uint32_t)(c & 1) * GB_STAGE;
        if (c + 1 < NC) {
            gb_load(Ahi, Alo, Bhi, Blo, m0, n0, (c + 1) * 32,
                    sb + (uint32_t)((c + 1) & 1) * GB_STAGE, tid);
            CP_WAIT(1);
        } else {
            CP_WAIT(0);
        }
        __syncthreads();

        #pragma unroll
        for (int kk = 0; kk < 32; kk += 16) {
            uint32_t aH[4][4], aL[4][4], bH[2][4], bL[2][4];
            #pragma unroll
            for (int mt = 0; mt < 4; mt++) {
                int row = wm * 64 + mt * 16 + lr + (ti & 1) * 8;
                int ch  = (kk >> 3) + (ti >> 1);
                uint32_t ad = sBase + (uint32_t)row * 64u
                            + (uint32_t)((ch ^ ((row >> 1) & 3)) << 4);
                ldsm4(aH[mt], ad);
                ldsm4(aL[mt], ad + 8192);
            }
            #pragma unroll
            for (int ng = 0; ng < 2; ng++) {
                int row = wn * 32 + ng * 16 + lr + (ti >> 1) * 8;
                int ch  = (kk >> 3) + (ti & 1);
                uint32_t bd = sBase + 16384u + (uint32_t)row * 64u
                            + (uint32_t)((ch ^ ((row >> 1) & 3)) << 4);
                ldsm4(bH[ng], bd);
                ldsm4(bL[ng], bd + 8192);
            }
            #pragma unroll
            for (int mt = 0; mt < 4; mt++)
                #pragma unroll
                for (int nt = 0; nt < 4; nt++) {
                    int ng = nt >> 1, hb = (nt & 1) * 2;
                    mma16816(acc[mt][nt], aH[mt], bH[ng][hb], bH[ng][hb + 1]);
                    mma16816(acc[mt][nt], aH[mt], bL[ng][hb], bL[ng][hb + 1]);
                    mma16816(acc[mt][nt], aL[mt], bH[ng][hb], bH[ng][hb + 1]);
                }
        }
        __syncthreads();
    }

    // Epilogue: direct global stores
    #pragma unroll
    for (int mt = 0; mt < 4; mt++) {
        #pragma unroll
        for (int nt = 0; nt < 4; nt++) {
            int row = m0 + wm * 64 + mt * 16 + (lane >> 2);
            int col = n0 + wn * 32 + nt * 8 + (lane & 3) * 2;
            float b0 = 0.f, b1 = 0.f;
            if (bias) { b0 = bias[col]; b1 = bias[col + 1]; }
            float2 v0 = make_float2(acc[mt][nt][0] + b0, acc[mt][nt][1] + b1);
            float2 v1 = make_float2(acc[mt][nt][2] + b0, acc[mt][nt][3] + b1);
            *(float2*)(C + (size_t)row * Dd + col)       = v0;
            *(float2*)(C + (size_t)(row + 8) * Dd + col) = v1;
        }
    }
}

// ---------------------------------------------------------------------------
// Flash attention, fp32, causal. BM=BN=64, 256 threads (16x16), 4x4 microtile.
// Outputs bf16 hi/lo split for the final GEMM.
// ---------------------------------------------------------------------------
#define ATT_PITCH 68
#define ATT_SMEM  (4 * 64 * ATT_PITCH * (int)sizeof(float))

__global__ __launch_bounds__(256) void attn_kernel() {
    extern __shared__ float sm[];
    float (*Qs)[ATT_PITCH]  = (float(*)[ATT_PITCH])(sm);
    float (*Kst)[ATT_PITCH] = (float(*)[ATT_PITCH])(sm + 64 * ATT_PITCH);
    float (*Vs)[ATT_PITCH]  = (float(*)[ATT_PITCH])(sm + 2 * 64 * ATT_PITCH);
    float (*Ps)[ATT_PITCH]  = (float(*)[ATT_PITCH])(sm + 3 * 64 * ATT_PITCH);

    int qb = blockIdx.x;
    int bh = blockIdx.y;
    int b  = bh >> 4;
    int h  = bh & 15;
    size_t base = (size_t)b * Ss * Dd + (size_t)h * HSs;
    const float* Qp = g_qp + base;
    const float* Kp = g_kp + base;
    const float* Vp = g_vp + base;
    __nv_bfloat16* Oh = g_attnhi + base;
    __nv_bfloat16* Ol = g_attnlo + base;
    int q0 = qb * 64;

    int tid = threadIdx.x;
    int tr = tid >> 4, tc = tid & 15;
    int tr4 = tr * 4, tc4 = tc * 4;

    for (int idx = tid; idx < 64 * 16; idx += 256) {
        int r = idx >> 4, c = (idx & 15) << 2;
        *(float4*)&Qs[r][c] = *(const float4*)(Qp + (size_t)(q0 + r) * Dd + c);
    }

    float m[4], l[4], o[4][4];
    #pragma unroll
    for (int i = 0; i < 4; i++) {
        m[i] = -1e30f; l[i] = 0.f;
        #pragma unroll
        for (int j = 0; j < 4; j++) o[i][j] = 0.f;
    }

    const float SC = 0.03125f;

    for (int kb = 0; kb <= qb; kb++) {
        int k0 = kb * 64;
        __syncthreads();
        for (int idx = tid; idx < 64 * 16; idx += 256) {
            int r = idx >> 4, c = (idx & 15) << 2;
            float4 kv = *(const float4*)(Kp + (size_t)(k0 + r) * Dd + c);
            Kst[c + 0][r] = kv.x;
            Kst[c + 1][r] = kv.y;
            Kst[c + 2][r] = kv.z;
            Kst[c + 3][r] = kv.w;
            *(float4*)&Vs[r][c] = *(const float4*)(Vp + (size_t)(k0 + r) * Dd + c);
        }
        __syncthreads();

        float s[4][4];
        #pragma unroll
        for (int i = 0; i < 4; i++)
            #pragma unroll
            for (int j = 0; j < 4; j++) s[i][j] = 0.f;

        #pragma unroll
        for (int e = 0; e < 64; e += 4) {
            float4 k0v = *(const float4*)&Kst[e + 0][tc4];
            float4 k1v = *(const float4*)&Kst[e + 1][tc4];
            float4 k2v = *(const float4*)&Kst[e + 2][tc4];
            float4 k3v = *(const float4*)&Kst[e + 3][tc4];
            #pragma unroll
            for (int i = 0; i < 4; i++) {
                float4 qv = *(const float4*)&Qs[tr4 + i][e];
                s[i][0] += qv.x*k0v.x + qv.y*k1v.x + qv.z*k2v.x + qv.w*k3v.x;
                s[i][1] += qv.x*k0v.y + qv.y*k1v.y + qv.z*k2v.y + qv.w*k3v.y;
                s[i][2] += qv.x*k0v.z + qv.y*k1v.z + qv.z*k2v.z + qv.w*k3v.z;
                s[i][3] += qv.x*k0v.w + qv.y*k1v.w + qv.z*k2v.w + qv.w*k3v.w;
            }
        }

        if (kb == qb) {
            #pragma unroll
            for (int i = 0; i < 4; i++)
                #pragma unroll
                for (int j = 0; j < 4; j++) {
                    int kg = k0 + tc4 + j;
                    int qg = q0 + tr4 + i;
                    s[i][j] = (kg <= qg) ? s[i][j] * SC : -1e30f;
                }
        } else {
            #pragma unroll
            for (int i = 0; i < 4; i++)
                #pragma unroll
                for (int j = 0; j < 4; j++) s[i][j] *= SC;
        }

        #pragma unroll
        for (int i = 0; i < 4; i++) {
            float mx = fmaxf(fmaxf(s[i][0], s[i][1]), fmaxf(s[i][2], s[i][3]));
            mx = fmaxf(mx, __shfl_xor_sync(0xffffffffu, mx, 1));
            mx = fmaxf(mx, __shfl_xor_sync(0xffffffffu, mx, 2));
            mx = fmaxf(mx, __shfl_xor_sync(0xffffffffu, mx, 4));
            mx = fmaxf(mx, __shfl_xor_sync(0xffffffffu, mx, 8));
            float mn = fmaxf(m[i], mx);
            float al = __expf(m[i] - mn);
            float p0 = __expf(s[i][0] - mn);
            float p1 = __expf(s[i][1] - mn);
            float p2 = __expf(s[i][2] - mn);
            float p3 = __expf(s[i][3] - mn);
            float rs = p0 + p1 + p2 + p3;
            rs += __shfl_xor_sync(0xffffffffu, rs, 1);
            rs += __shfl_xor_sync(0xffffffffu, rs, 2);
            rs += __shfl_xor_sync(0xffffffffu, rs, 4);
            rs += __shfl_xor_sync(0xffffffffu, rs, 8);
            l[i] = l[i] * al + rs;
            m[i] = mn;
            o[i][0] *= al; o[i][1] *= al; o[i][2] *= al; o[i][3] *= al;
            *(float4*)&Ps[tr4 + i][tc4] = make_float4(p0, p1, p2, p3);
        }
        __syncthreads();

        #pragma unroll 8
        for (int kk = 0; kk < 64; kk++) {
            float4 vv = *(const float4*)&Vs[kk][tc4];
            #pragma unroll
            for (int i = 0; i < 4; i++) {
                float p = Ps[tr4 + i][kk];
                o[i][0] += p * vv.x;
                o[i][1] += p * vv.y;
                o[i][2] += p * vv.z;
                o[i][3] += p * vv.w;
            }
        }
    }

    #pragma unroll
    for (int i = 0; i < 4; i++) {
        float inv = 1.0f / l[i];
        float v0 = o[i][0] * inv, v1 = o[i][1] * inv;
        float v2 = o[i][2] * inv, v3 = o[i][3] * inv;
        __nv_bfloat16 h0, l0, h1, l1, h2, l2, h3, l3;
        bf_split(v0, h0, l0); bf_split(v1, h1, l1);
        bf_split(v2, h2, l2); bf_split(v3, h3, l3);
        size_t off = (size_t)(q0 + tr4 + i) * Dd + tc4;
        ((__nv_bfloat162*)(Oh + off))[0] = __nv_bfloat162{h0, h1};
        ((__nv_bfloat162*)(Oh + off))[1] = __nv_bfloat162{h2, h3};
        ((__nv_bfloat162*)(Ol + off))[0] = __nv_bfloat162{l0, l1};
        ((__nv_bfloat162*)(Ol + off))[1] = __nv_bfloat162{l2, l3};
    }
}

// ---------------------------------------------------------------------------
// Host launch (graph-capturable: kernels only)
// ---------------------------------------------------------------------------
extern "C" void kernel_launch(void* const* d_in, const int* in_sizes, int n_in,
                              void* d_out, int out_size) {
    const float* v   = (const float*)d_in[0];
    const float* k   = (const float*)d_in[1];
    const float* q   = (const float*)d_in[2];
    const float* lng = (const float*)d_in[4];
    const float* lnb = (const float*)d_in[5];
    const float* Wq  = (const float*)d_in[6];
    const float* Wk  = (const float*)d_in[7];
    const float* Wv  = (const float*)d_in[8];
    const float* Wp  = (const float*)d_in[9];
    const float* bp  = (const float*)d_in[10];
    float* out = (float*)d_out;

    void *p_lnvhi, *p_lnvlo, *p_lnkhi, *p_lnklo, *p_lnqhi, *p_lnqlo;
    void *p_qp, *p_kp, *p_vp, *p_attnhi, *p_attnlo;
    void *p_wqhi, *p_wqlo, *p_wkhi, *p_wklo, *p_wvhi, *p_wvlo, *p_wphi, *p_wplo;
    cudaGetSymbolAddress(&p_lnvhi, g_lnvhi);
    cudaGetSymbolAddress(&p_lnvlo, g_lnvlo);
    cudaGetSymbolAddress(&p_lnkhi, g_lnkhi);
    cudaGetSymbolAddress(&p_lnklo, g_lnklo);
    cudaGetSymbolAddress(&p_lnqhi, g_lnqhi);
    cudaGetSymbolAddress(&p_lnqlo, g_lnqlo);
    cudaGetSymbolAddress(&p_qp,    g_qp);
    cudaGetSymbolAddress(&p_kp,    g_kp);
    cudaGetSymbolAddress(&p_vp,    g_vp);
    cudaGetSymbolAddress(&p_attnhi, g_attnhi);
    cudaGetSymbolAddress(&p_attnlo, g_attnlo);
    cudaGetSymbolAddress(&p_wqhi, g_Wqhi);
    cudaGetSymbolAddress(&p_wqlo, g_Wqlo);
    cudaGetSymbolAddress(&p_wkhi, g_Wkhi);
    cudaGetSymbolAddress(&p_wklo, g_Wklo);
    cudaGetSymbolAddress(&p_wvhi, g_Wvhi);
    cudaGetSymbolAddress(&p_wvlo, g_Wvlo);
    cudaGetSymbolAddress(&p_wphi, g_Wphi);
    cudaGetSymbolAddress(&p_wplo, g_Wplo);

    cudaFuncSetAttribute(attn_kernel,
                         cudaFuncAttributeMaxDynamicSharedMemorySize, ATT_SMEM);
    cudaFuncSetAttribute(gemm_bf3_kernel,
                         cudaFuncAttributeMaxDynamicSharedMemorySize, GB_SMEM);

    reorder_kernel<<<(Dd * Dd) / 256, 256>>>(Wq, Wk, Wv, Wp);
    ln_kernel<<<dim3(MM, 3), 256>>>(v, k, q, lng, lnb);

    dim3 ggrid(Dd / 128, MM / 128);
    gemm_bf3_kernel<<<ggrid, 256, GB_SMEM>>>(
        (const __nv_bfloat16*)p_lnqhi, (const __nv_bfloat16*)p_lnqlo,
        (const __nv_bfloat16*)p_wqhi,  (const __nv_bfloat16*)p_wqlo,
        (float*)p_qp, nullptr);
    gemm_bf3_kernel<<<ggrid, 256, GB_SMEM>>>(
        (const __nv_bfloat16*)p_lnkhi, (const __nv_bfloat16*)p_lnklo,
        (const __nv_bfloat16*)p_wkhi,  (const __nv_bfloat16*)p_wklo,
        (float*)p_kp, nullptr);
    gemm_bf3_kernel<<<ggrid, 256, GB_SMEM>>>(
        (const __nv_bfloat16*)p_lnvhi, (const __nv_bfloat16*)p_lnvlo,
        (const __nv_bfloat16*)p_wvhi,  (const __nv_bfloat16*)p_wvlo,
        (float*)p_vp, nullptr);
    attn_kernel<<<dim3(Ss / 64, Bb * Hh), 256, ATT_SMEM>>>();
    gemm_bf3_kernel<<<ggrid, 256, GB_SMEM>>>(
        (const __nv_bfloat16*)p_attnhi, (const __nv_bfloat16*)p_attnlo,
        (const __nv_bfloat16*)p_wphi,   (const __nv_bfloat16*)p_wplo,
        out, bp);
}

// round 6
// speedup vs baseline: 3.0558x; 2.0456x over previous
#include <cuda_runtime.h>
#include <cuda_bf16.h>
#include <cuda_fp16.h>
#include <cstdint>
#include <math.h>

// Problem constants
#define Bb  4
#define Ss  2048
#define Dd  1024
#define Hh  16
#define HSs 64
#define MM  (Bb*Ss)   // 8192 rows

// ---------------------------------------------------------------------------
// PTX helpers (baseline PTX only — harness emits compute_103, no 'a' features)
// ---------------------------------------------------------------------------
__device__ __forceinline__ uint32_t smem_u32(const void* p) {
    uint32_t a;
    asm("{ .reg .u64 t; cvta.to.shared.u64 t, %1; cvt.u32.u64 %0, t; }"
        : "=r"(a) : "l"(p));
    return a;
}

#define CP_ASYNC16(smem_addr, gptr) \
    asm volatile("cp.async.cg.shared.global [%0], [%1], 16;" \
                 :: "r"((uint32_t)(smem_addr)), "l"(gptr) : "memory")
#define CP_COMMIT() asm volatile("cp.async.commit_group;" ::: "memory")
#define CP_WAIT(n)  asm volatile("cp.async.wait_group %0;" :: "n"(n) : "memory")

__device__ __forceinline__ void ldsm4(uint32_t r[4], uint32_t addr) {
    asm volatile("ldmatrix.sync.aligned.m8n8.x4.shared.b16 {%0,%1,%2,%3}, [%4];"
                 : "=r"(r[0]), "=r"(r[1]), "=r"(r[2]), "=r"(r[3]) : "r"(addr));
}

// bf16 variant (projection GEMMs)
__device__ __forceinline__ void mma16816(float c[4], const uint32_t a[4],
                                         uint32_t b0, uint32_t b1) {
    asm volatile(
        "mma.sync.aligned.m16n8k16.row.col.f32.bf16.bf16.f32 "
        "{%0,%1,%2,%3}, {%4,%5,%6,%7}, {%8,%9}, {%0,%1,%2,%3};"
        : "+f"(c[0]), "+f"(c[1]), "+f"(c[2]), "+f"(c[3])
        : "r"(a[0]), "r"(a[1]), "r"(a[2]), "r"(a[3]), "r"(b0), "r"(b1));
}

// fp16 variant (attention)
__device__ __forceinline__ void mma16816h(float c[4], const uint32_t a[4],
                                          uint32_t b0, uint32_t b1) {
    asm volatile(
        "mma.sync.aligned.m16n8k16.row.col.f32.f16.f16.f32 "
        "{%0,%1,%2,%3}, {%4,%5,%6,%7}, {%8,%9}, {%0,%1,%2,%3};"
        : "+f"(c[0]), "+f"(c[1]), "+f"(c[2]), "+f"(c[3])
        : "r"(a[0]), "r"(a[1]), "r"(a[2]), "r"(a[3]), "r"(b0), "r"(b1));
}

__device__ __forceinline__ uint32_t packh2(float a, float b) {
    __half2 h = __floats2half2_rn(a, b);
    return *(uint32_t*)&h;
}

// ---------------------------------------------------------------------------
// Device scratch
// ---------------------------------------------------------------------------
__device__ __nv_bfloat16 g_lnvhi[MM*Dd];
__device__ __nv_bfloat16 g_lnvlo[MM*Dd];
__device__ __nv_bfloat16 g_lnkhi[MM*Dd];
__device__ __nv_bfloat16 g_lnklo[MM*Dd];
__device__ __nv_bfloat16 g_lnqhi[MM*Dd];
__device__ __nv_bfloat16 g_lnqlo[MM*Dd];
__device__ __half g_q16[MM*Dd];            // projected Q * D^-0.5, fp16
__device__ __half g_k16[MM*Dd];            // projected K, fp16
__device__ float  g_vp [MM*Dd];            // projected V, fp32
__device__ __half g_vt16[Bb*Hh*HSs*Ss];    // V transposed: [(b*16+h)*64+e][s]
__device__ __nv_bfloat16 g_attnhi[MM*Dd];
__device__ __nv_bfloat16 g_attnlo[MM*Dd];
__device__ __nv_bfloat16 g_Wqhi[Dd*Dd];
__device__ __nv_bfloat16 g_Wqlo[Dd*Dd];
__device__ __nv_bfloat16 g_Wkhi[Dd*Dd];
__device__ __nv_bfloat16 g_Wklo[Dd*Dd];
__device__ __nv_bfloat16 g_Wvhi[Dd*Dd];
__device__ __nv_bfloat16 g_Wvlo[Dd*Dd];
__device__ __nv_bfloat16 g_Wphi[Dd*Dd];
__device__ __nv_bfloat16 g_Wplo[Dd*Dd];

__device__ __forceinline__ void bf_split(float x, __nv_bfloat16& h, __nv_bfloat16& l) {
    h = __float2bfloat16(x);
    l = __float2bfloat16(x - __bfloat162float(h));
}

// ---------------------------------------------------------------------------
// Weight reorder to [N,K] (K contiguous) + bf16 hi/lo split.
// ---------------------------------------------------------------------------
__global__ void reorder_kernel(const float* __restrict__ Wq,
                               const float* __restrict__ Wk,
                               const float* __restrict__ Wv,
                               const float* __restrict__ Wp) {
    int idx = blockIdx.x * 256 + threadIdx.x;   // n*1024 + k
    int n = idx >> 10;
    int k = idx & 1023;
    int h = n >> 6;
    int e = n & 63;
    int src = h * (Dd * HSs) + k * HSs + e;
    __nv_bfloat16 hh, ll;
    bf_split(Wq[src], hh, ll); g_Wqhi[idx] = hh; g_Wqlo[idx] = ll;
    bf_split(Wk[src], hh, ll); g_Wkhi[idx] = hh; g_Wklo[idx] = ll;
    bf_split(Wv[src], hh, ll); g_Wvhi[idx] = hh; g_Wvlo[idx] = ll;
    bf_split(Wp[idx], hh, ll); g_Wphi[idx] = hh; g_Wplo[idx] = ll;
}

// ---------------------------------------------------------------------------
// Fused layernorm for v,k,q  (grid: (MM, 3), 256 threads) + bf16 hi/lo split
// ---------------------------------------------------------------------------
__global__ __launch_bounds__(256) void ln_kernel(const float* __restrict__ v,
                                                 const float* __restrict__ k,
                                                 const float* __restrict__ q,
                                                 const float* __restrict__ g,
                                                 const float* __restrict__ b) {
    int row   = blockIdx.x;
    int which = blockIdx.y;
    const float* x;
    __nv_bfloat16 *yh, *yl;
    if (which == 0)      { x = v; yh = g_lnvhi; yl = g_lnvlo; }
    else if (which == 1) { x = k; yh = g_lnkhi; yl = g_lnklo; }
    else                 { x = q; yh = g_lnqhi; yl = g_lnqlo; }
    x  += (size_t)row * Dd;
    yh += (size_t)row * Dd;
    yl += (size_t)row * Dd;

    int t = threadIdx.x;
    float4 xv = ((const float4*)x)[t];
    float s1 = xv.x + xv.y + xv.z + xv.w;
    float s2 = xv.x*xv.x + xv.y*xv.y + xv.z*xv.z + xv.w*xv.w;
    #pragma unroll
    for (int off = 16; off; off >>= 1) {
        s1 += __shfl_xor_sync(0xffffffffu, s1, off);
        s2 += __shfl_xor_sync(0xffffffffu, s2, off);
    }
    __shared__ float w1[8], w2[8];
    __shared__ float smu, srs;
    int wid = t >> 5, lid = t & 31;
    if (lid == 0) { w1[wid] = s1; w2[wid] = s2; }
    __syncthreads();
    if (t == 0) {
        float t1 = 0.f, t2 = 0.f;
        #pragma unroll
        for (int i = 0; i < 8; i++) { t1 += w1[i]; t2 += w2[i]; }
        float mu  = t1 * (1.0f / Dd);
        float var = t2 * (1.0f / Dd) - mu * mu;
        smu = mu;
        srs = rsqrtf(var + 1e-5f);
    }
    __syncthreads();
    float mu = smu, rs = srs;
    float4 gv = ((const float4*)g)[t];
    float4 bv = ((const float4*)b)[t];
    float y0 = (xv.x - mu) * rs * gv.x + bv.x;
    float y1 = (xv.y - mu) * rs * gv.y + bv.y;
    float y2 = (xv.z - mu) * rs * gv.z + bv.z;
    float y3 = (xv.w - mu) * rs * gv.w + bv.w;
    __nv_bfloat16 h0, l0, h1, l1, h2, l2, h3, l3;
    bf_split(y0, h0, l0); bf_split(y1, h1, l1);
    bf_split(y2, h2, l2); bf_split(y3, h3, l3);
    __nv_bfloat162* yh2 = (__nv_bfloat162*)yh;
    __nv_bfloat162* yl2 = (__nv_bfloat162*)yl;
    yh2[2*t]   = __nv_bfloat162{h0, h1};
    yh2[2*t+1] = __nv_bfloat162{h2, h3};
    yl2[2*t]   = __nv_bfloat162{l0, l1};
    yl2[2*t+1] = __nv_bfloat162{l2, l3};
}

// ---------------------------------------------------------------------------
// bf16x3 mma.sync GEMM: outputs fp32 C (optional) and/or fp16 C16*scale.
// ---------------------------------------------------------------------------
#define GB_STAGE 32768
#define GB_SMEM  (2 * GB_STAGE)

__device__ __forceinline__ void gb_load(const __nv_bfloat16* Ahi,
                                        const __nv_bfloat16* Alo,
                                        const __nv_bfloat16* Bhi,
                                        const __nv_bfloat16* Blo,
                                        int m0, int n0, int k0,
                                        uint32_t stage_base, int tid) {
    #pragma unroll
    for (int i = 0; i < 8; i++) {
        int gid = tid + i * 256;          // 0..2047
        int arr = gid >> 9;               // 0:AH 1:AL 2:BH 3:BL
        int idx = gid & 511;
        int row = idx >> 2;               // 0..127
        int c   = idx & 3;                // 16B chunk in 64B row
        uint32_t dst = stage_base + (uint32_t)arr * 8192u
                     + (uint32_t)row * 64u + (uint32_t)((c ^ ((row >> 1) & 3)) << 4);
        const __nv_bfloat16* p = (arr & 2) ? ((arr & 1) ? Blo : Bhi)
                                           : ((arr & 1) ? Alo : Ahi);
        int g0 = (arr & 2) ? n0 : m0;
        CP_ASYNC16(dst, p + (size_t)(g0 + row) * Dd + k0 + c * 8);
    }
    CP_COMMIT();
}

__global__ __launch_bounds__(256, 1) void gemm_bf3_kernel(
        const __nv_bfloat16* __restrict__ Ahi,
        const __nv_bfloat16* __restrict__ Alo,
        const __nv_bfloat16* __restrict__ Bhi,
        const __nv_bfloat16* __restrict__ Blo,
        float* __restrict__ C,
        const float* __restrict__ bias,
        __half* __restrict__ C16,
        float sc16) {
    extern __shared__ char smem[];
    uint32_t sb = smem_u32(smem);

    int tid  = threadIdx.x;
    int wid  = tid >> 5;
    int lane = tid & 31;
    int m0 = blockIdx.y * 128;
    int n0 = blockIdx.x * 128;
    int wm = wid & 1;
    int wn = wid >> 1;

    float acc[4][4][4];
    #pragma unroll
    for (int i = 0; i < 4; i++)
        #pragma unroll
        for (int j = 0; j < 4; j++)
            #pragma unroll
            for (int r = 0; r < 4; r++) acc[i][j][r] = 0.f;

    gb_load(Ahi, Alo, Bhi, Blo, m0, n0, 0, sb, tid);

    int ti = lane >> 3, lr = lane & 7;

    const int NC = Dd / 32;
    for (int c = 0; c < NC; c++) {
        uint32_t sBase = sb + (uint32_t)(c & 1) * GB_STAGE;
        if (c + 1 < NC) {
            gb_load(Ahi, Alo, Bhi, Blo, m0, n0, (c + 1) * 32,
                    sb + (uint32_t)((c + 1) & 1) * GB_STAGE, tid);
            CP_WAIT(1);
        } else {
            CP_WAIT(0);
        }
        __syncthreads();

        #pragma unroll
        for (int kk = 0; kk < 32; kk += 16) {
            uint32_t aH[4][4], aL[4][4], bH[2][4], bL[2][4];
            #pragma unroll
            for (int mt = 0; mt < 4; mt++) {
                int row = wm * 64 + mt * 16 + lr + (ti & 1) * 8;
                int ch  = (kk >> 3) + (ti >> 1);
                uint32_t ad = sBase + (uint32_t)row * 64u
                            + (uint32_t)((ch ^ ((row >> 1) & 3)) << 4);
                ldsm4(aH[mt], ad);
                ldsm4(aL[mt], ad + 8192);
            }
            #pragma unroll
            for (int ng = 0; ng < 2; ng++) {
                int row = wn * 32 + ng * 16 + lr + (ti >> 1) * 8;
                int ch  = (kk >> 3) + (ti & 1);
                uint32_t bd = sBase + 16384u + (uint32_t)row * 64u
                            + (uint32_t)((ch ^ ((row >> 1) & 3)) << 4);
                ldsm4(bH[ng], bd);
                ldsm4(bL[ng], bd + 8192);
            }
            #pragma unroll
            for (int mt = 0; mt < 4; mt++)
                #pragma unroll
                for (int nt = 0; nt < 4; nt++) {
                    int ng = nt >> 1, hb = (nt & 1) * 2;
                    mma16816(acc[mt][nt], aH[mt], bH[ng][hb], bH[ng][hb + 1]);
                    mma16816(acc[mt][nt], aH[mt], bL[ng][hb], bL[ng][hb + 1]);
                    mma16816(acc[mt][nt], aL[mt], bH[ng][hb], bH[ng][hb + 1]);
                }
        }
        __syncthreads();
    }

    #pragma unroll
    for (int mt = 0; mt < 4; mt++) {
        #pragma unroll
        for (int nt = 0; nt < 4; nt++) {
            int row = m0 + wm * 64 + mt * 16 + (lane >> 2);
            int col = n0 + wn * 32 + nt * 8 + (lane & 3) * 2;
            if (C) {
                float b0 = 0.f, b1 = 0.f;
                if (bias) { b0 = bias[col]; b1 = bias[col + 1]; }
                *(float2*)(C + (size_t)row * Dd + col) =
                    make_float2(acc[mt][nt][0] + b0, acc[mt][nt][1] + b1);
                *(float2*)(C + (size_t)(row + 8) * Dd + col) =
                    make_float2(acc[mt][nt][2] + b0, acc[mt][nt][3] + b1);
            }
            if (C16) {
                uint32_t h0 = packh2(acc[mt][nt][0] * sc16, acc[mt][nt][1] * sc16);
                uint32_t h1 = packh2(acc[mt][nt][2] * sc16, acc[mt][nt][3] * sc16);
                *(uint32_t*)(C16 + (size_t)row * Dd + col)       = h0;
                *(uint32_t*)(C16 + (size_t)(row + 8) * Dd + col) = h1;
            }
        }
    }
}

// ---------------------------------------------------------------------------
// V transpose: g_vp fp32 [token][h*64+e] -> g_vt16 fp16 [(b*16+h)*64+e][s]
// grid (S/64, B*H), 256 threads
// ---------------------------------------------------------------------------
__global__ __launch_bounds__(256) void vt_kernel() {
    __shared__ float ts[64][65];
    int s0 = blockIdx.x * 64;
    int bh = blockIdx.y;
    int b  = bh >> 4;
    int h  = bh & 15;
    int tid = threadIdx.x;
    #pragma unroll
    for (int i = 0; i < 16; i++) {
        int idx = tid + i * 256;
        int r = idx >> 6, e = idx & 63;
        ts[r][e] = g_vp[(size_t)(b * Ss + s0 + r) * Dd + h * HSs + e];
    }
    __syncthreads();
    #pragma unroll
    for (int i = 0; i < 16; i++) {
        int idx = tid + i * 256;
        int e = idx >> 6, t = idx & 63;
        g_vt16[((size_t)bh * HSs + e) * Ss + s0 + t] = __float2half(ts[t][e]);
    }
}

// ---------------------------------------------------------------------------
// Flash attention v2: fp16 mma.sync, causal. BM=128, BN=64, 8 warps.
// Q pre-scaled by D^-0.5 in fp16. Output bf16 hi/lo for final GEMM.
// smem: Q 16K | K 8K | VT 8K = 32K. Swizzle: 128B rows, chunk ^ (row&7).
// grid: (S/128, B*H)
// ---------------------------------------------------------------------------
#define AT_Q 0
#define AT_K 16384
#define AT_V 24576
#define AT2_SMEM 32768

__global__ __launch_bounds__(256, 1) void attn2_kernel() {
    extern __shared__ char smem[];
    uint32_t sb = smem_u32(smem);
    int qb = blockIdx.x;
    int bh = blockIdx.y;
    int b  = bh >> 4;
    int h  = bh & 15;
    int q0 = qb * 128;

    int tid  = threadIdx.x;
    int wid  = tid >> 5;
    int lane = tid & 31;
    int lr = lane & 7, ti = lane >> 3;

    // Load Q tile (128 x 64 fp16)
    #pragma unroll
    for (int i = 0; i < 4; i++) {
        int idx = tid + i * 256;
        int row = idx >> 3, c = idx & 7;
        uint32_t dst = sb + AT_Q + (uint32_t)row * 128u + (uint32_t)((c ^ (row & 7)) << 4);
        CP_ASYNC16(dst, g_q16 + (size_t)(b * Ss + q0 + row) * Dd + h * HSs + c * 8);
    }
    CP_COMMIT();

    float m0 = -1e30f, m1 = -1e30f, l0 = 0.f, l1 = 0.f;
    float O[8][4];
    #pragma unroll
    for (int f = 0; f < 8; f++)
        #pragma unroll
        for (int r = 0; r < 4; r++) O[f][r] = 0.f;

    int NB = 2 * qb + 2;
    for (int kb = 0; kb < NB; kb++) {
        int k0 = kb * 64;
        __syncthreads();
        #pragma unroll
        for (int i = 0; i < 2; i++) {
            int idx = tid + i * 256;
            int row = idx >> 3, c = idx & 7;
            uint32_t sw = (uint32_t)((c ^ (row & 7)) << 4);
            CP_ASYNC16(sb + AT_K + (uint32_t)row * 128u + sw,
                       g_k16 + (size_t)(b * Ss + k0 + row) * Dd + h * HSs + c * 8);
            CP_ASYNC16(sb + AT_V + (uint32_t)row * 128u + sw,
                       g_vt16 + ((size_t)bh * HSs + row) * Ss + k0 + c * 8);
        }
        CP_COMMIT();
        CP_WAIT(0);
        __syncthreads();

        // S = Q K^T
        uint32_t aQ[4][4];
        #pragma unroll
        for (int ks = 0; ks < 4; ks++) {
            int row = wid * 16 + lr + (ti & 1) * 8;
            int ch  = 2 * ks + (ti >> 1);
            ldsm4(aQ[ks], sb + AT_Q + (uint32_t)row * 128u
                          + (uint32_t)((ch ^ (row & 7)) << 4));
        }
        float S[8][4];
        #pragma unroll
        for (int f = 0; f < 8; f++)
            #pragma unroll
            for (int r = 0; r < 4; r++) S[f][r] = 0.f;

        #pragma unroll
        for (int nt = 0; nt < 4; nt++) {
            int krow = nt * 16 + lr + (ti >> 1) * 8;
            #pragma unroll
            for (int ks = 0; ks < 4; ks++) {
                int ch = 2 * ks + (ti & 1);
                uint32_t bK[4];
                ldsm4(bK, sb + AT_K + (uint32_t)krow * 128u
                          + (uint32_t)((ch ^ (krow & 7)) << 4));
                mma16816h(S[2 * nt],     aQ[ks], bK[0], bK[1]);
                mma16816h(S[2 * nt + 1], aQ[ks], bK[2], bK[3]);
            }
        }

        // causal mask (diagonal band only)
        if (kb >= 2 * qb) {
            int r0 = q0 + wid * 16 + (lane >> 2);
            #pragma unroll
            for (int f = 0; f < 8; f++) {
                int kg = k0 + f * 8 + 2 * (lane & 3);
                if (kg     > r0)     S[f][0] = -1e30f;
                if (kg + 1 > r0)     S[f][1] = -1e30f;
                if (kg     > r0 + 8) S[f][2] = -1e30f;
                if (kg + 1 > r0 + 8) S[f][3] = -1e30f;
            }
        }

        // online softmax (rows r0=lane/4, r1=r0+8; quad lanes share rows)
        float mx0 = -1e30f, mx1 = -1e30f;
        #pragma unroll
        for (int f = 0; f < 8; f++) {
            mx0 = fmaxf(mx0, fmaxf(S[f][0], S[f][1]));
            mx1 = fmaxf(mx1, fmaxf(S[f][2], S[f][3]));
        }
        mx0 = fmaxf(mx0, __shfl_xor_sync(0xffffffffu, mx0, 1));
        mx0 = fmaxf(mx0, __shfl_xor_sync(0xffffffffu, mx0, 2));
        mx1 = fmaxf(mx1, __shfl_xor_sync(0xffffffffu, mx1, 1));
        mx1 = fmaxf(mx1, __shfl_xor_sync(0xffffffffu, mx1, 2));
        float mn0 = fmaxf(m0, mx0), mn1 = fmaxf(m1, mx1);
        float al0 = __expf(m0 - mn0), al1 = __expf(m1 - mn1);
        float rs0 = 0.f, rs1 = 0.f;
        #pragma unroll
        for (int f = 0; f < 8; f++) {
            S[f][0] = __expf(S[f][0] - mn0);
            S[f][1] = __expf(S[f][1] - mn0);
            S[f][2] = __expf(S[f][2] - mn1);
            S[f][3] = __expf(S[f][3] - mn1);
            rs0 += S[f][0] + S[f][1];
            rs1 += S[f][2] + S[f][3];
        }
        rs0 += __shfl_xor_sync(0xffffffffu, rs0, 1);
        rs0 += __shfl_xor_sync(0xffffffffu, rs0, 2);
        rs1 += __shfl_xor_sync(0xffffffffu, rs1, 1);
        rs1 += __shfl_xor_sync(0xffffffffu, rs1, 2);
        l0 = l0 * al0 + rs0;
        l1 = l1 * al1 + rs1;
        m0 = mn0; m1 = mn1;
        #pragma unroll
        for (int f = 0; f < 8; f++) {
            O[f][0] *= al0; O[f][1] *= al0;
            O[f][2] *= al1; O[f][3] *= al1;
        }

        // P fragments (C-frag -> A-frag identity)
        uint32_t aP[4][4];
        #pragma unroll
        for (int f2 = 0; f2 < 4; f2++) {
            aP[f2][0] = packh2(S[2 * f2][0],     S[2 * f2][1]);
            aP[f2][1] = packh2(S[2 * f2][2],     S[2 * f2][3]);
            aP[f2][2] = packh2(S[2 * f2 + 1][0], S[2 * f2 + 1][1]);
            aP[f2][3] = packh2(S[2 * f2 + 1][2], S[2 * f2 + 1][3]);
        }

        // O += P V  (B = V^T tile, rows = e, K-major over keys)
        #pragma unroll
        for (int nt = 0; nt < 4; nt++) {
            int vrow = nt * 16 + lr + (ti >> 1) * 8;
            #pragma unroll
            for (int f2 = 0; f2 < 4; f2++) {
                int ch = 2 * f2 + (ti & 1);
                uint32_t bV[4];
                ldsm4(bV, sb + AT_V + (uint32_t)vrow * 128u
                          + (uint32_t)((ch ^ (vrow & 7)) << 4));
                mma16816h(O[2 * nt],     aP[f2], bV[0], bV[1]);
                mma16816h(O[2 * nt + 1], aP[f2], bV[2], bV[3]);
            }
        }
    }

    // Epilogue: normalize + bf16 hi/lo split
    float inv0 = 1.0f / l0, inv1 = 1.0f / l1;
    int row0 = q0 + wid * 16 + (lane >> 2);
    #pragma unroll
    for (int f = 0; f < 8; f++) {
        int col = h * HSs + f * 8 + 2 * (lane & 3);
        float v00 = O[f][0] * inv0, v01 = O[f][1] * inv0;
        float v10 = O[f][2] * inv1, v11 = O[f][3] * inv1;
        __nv_bfloat16 h00, l00, h01, l01, h10, l10, h11, l11;
        bf_split(v00, h00, l00); bf_split(v01, h01, l01);
        bf_split(v10, h10, l10); bf_split(v11, h11, l11);
        size_t o0 = (size_t)(b * Ss + row0) * Dd + col;
        size_t o1 = (size_t)(b * Ss + row0 + 8) * Dd + col;
        *(__nv_bfloat162*)(g_attnhi + o0) = __nv_bfloat162{h00, h01};
        *(__nv_bfloat162*)(g_attnlo + o0) = __nv_bfloat162{l00, l01};
        *(__nv_bfloat162*)(g_attnhi + o1) = __nv_bfloat162{h10, h11};
        *(__nv_bfloat162*)(g_attnlo + o1) = __nv_bfloat162{l10, l11};
    }
}

// ---------------------------------------------------------------------------
// Host launch (graph-capturable: kernels only)
// ---------------------------------------------------------------------------
extern "C" void kernel_launch(void* const* d_in, const int* in_sizes, int n_in,
                              void* d_out, int out_size) {
    const float* v   = (const float*)d_in[0];
    const float* k   = (const float*)d_in[1];
    const float* q   = (const float*)d_in[2];
    const float* lng = (const float*)d_in[4];
    const float* lnb = (const float*)d_in[5];
    const float* Wq  = (const float*)d_in[6];
    const float* Wk  = (const float*)d_in[7];
    const float* Wv  = (const float*)d_in[8];
    const float* Wp  = (const float*)d_in[9];
    const float* bp  = (const float*)d_in[10];
    float* out = (float*)d_out;

    void *p_lnvhi, *p_lnvlo, *p_lnkhi, *p_lnklo, *p_lnqhi, *p_lnqlo;
    void *p_q16, *p_k16, *p_vp, *p_attnhi, *p_attnlo;
    void *p_wqhi, *p_wqlo, *p_wkhi, *p_wklo, *p_wvhi, *p_wvlo, *p_wphi, *p_wplo;
    cudaGetSymbolAddress(&p_lnvhi, g_lnvhi);
    cudaGetSymbolAddress(&p_lnvlo, g_lnvlo);
    cudaGetSymbolAddress(&p_lnkhi, g_lnkhi);
    cudaGetSymbolAddress(&p_lnklo, g_lnklo);
    cudaGetSymbolAddress(&p_lnqhi, g_lnqhi);
    cudaGetSymbolAddress(&p_lnqlo, g_lnqlo);
    cudaGetSymbolAddress(&p_q16,   g_q16);
    cudaGetSymbolAddress(&p_k16,   g_k16);
    cudaGetSymbolAddress(&p_vp,    g_vp);
    cudaGetSymbolAddress(&p_attnhi, g_attnhi);
    cudaGetSymbolAddress(&p_attnlo, g_attnlo);
    cudaGetSymbolAddress(&p_wqhi, g_Wqhi);
    cudaGetSymbolAddress(&p_wqlo, g_Wqlo);
    cudaGetSymbolAddress(&p_wkhi, g_Wkhi);
    cudaGetSymbolAddress(&p_wklo, g_Wklo);
    cudaGetSymbolAddress(&p_wvhi, g_Wvhi);
    cudaGetSymbolAddress(&p_wvlo, g_Wvlo);
    cudaGetSymbolAddress(&p_wphi, g_Wphi);
    cudaGetSymbolAddress(&p_wplo, g_Wplo);

    cudaFuncSetAttribute(gemm_bf3_kernel,
                         cudaFuncAttributeMaxDynamicSharedMemorySize, GB_SMEM);
    cudaFuncSetAttribute(attn2_kernel,
                         cudaFuncAttributeMaxDynamicSharedMemorySize, AT2_SMEM);

    reorder_kernel<<<(Dd * Dd) / 256, 256>>>(Wq, Wk, Wv, Wp);
    ln_kernel<<<dim3(MM, 3), 256>>>(v, k, q, lng, lnb);

    dim3 ggrid(Dd / 128, MM / 128);
    // Q: fp16 output pre-scaled by D^-0.5
    gemm_bf3_kernel<<<ggrid, 256, GB_SMEM>>>(
        (const __nv_bfloat16*)p_lnqhi, (const __nv_bfloat16*)p_lnqlo,
        (const __nv_bfloat16*)p_wqhi,  (const __nv_bfloat16*)p_wqlo,
        nullptr, nullptr, (__half*)p_q16, 0.03125f);
    // K: fp16 output
    gemm_bf3_kernel<<<ggrid, 256, GB_SMEM>>>(
        (const __nv_bfloat16*)p_lnkhi, (const __nv_bfloat16*)p_lnklo,
        (const __nv_bfloat16*)p_wkhi,  (const __nv_bfloat16*)p_wklo,
        nullptr, nullptr, (__half*)p_k16, 1.0f);
    // V: fp32 output (transposed+converted next)
    gemm_bf3_kernel<<<ggrid, 256, GB_SMEM>>>(
        (const __nv_bfloat16*)p_lnvhi, (const __nv_bfloat16*)p_lnvlo,
        (const __nv_bfloat16*)p_wvhi,  (const __nv_bfloat16*)p_wvlo,
        (float*)p_vp, nullptr, nullptr, 1.0f);
    vt_kernel<<<dim3(Ss / 64, Bb * Hh), 256>>>();
    attn2_kernel<<<dim3(Ss / 128, Bb * Hh), 256, AT2_SMEM>>>();
    // Output projection (fp32 out + bias)
    gemm_bf3_kernel<<<ggrid, 256, GB_SMEM>>>(
        (const __nv_bfloat16*)p_attnhi, (const __nv_bfloat16*)p_attnlo,
        (const __nv_bfloat16*)p_wphi,   (const __nv_bfloat16*)p_wplo,
        out, bp, nullptr, 1.0f);
}

// round 8
// speedup vs baseline: 4.2796x; 1.4005x over previous
#include <cuda_runtime.h>
#include <cuda_fp16.h>
#include <cstdint>
#include <math.h>

// Problem constants
#define Bb  4
#define Ss  2048
#define Dd  1024
#define Hh  16
#define HSs 64
#define MM  (Bb*Ss)   // 8192 rows

// ---------------------------------------------------------------------------
// PTX helpers (baseline PTX only — harness emits compute_103, no 'a' features)
// ---------------------------------------------------------------------------
__device__ __forceinline__ uint32_t smem_u32(const void* p) {
    uint32_t a;
    asm("{ .reg .u64 t; cvta.to.shared.u64 t, %1; cvt.u32.u64 %0, t; }"
        : "=r"(a) : "l"(p));
    return a;
}

#define CP_ASYNC16(smem_addr, gptr) \
    asm volatile("cp.async.cg.shared.global [%0], [%1], 16;" \
                 :: "r"((uint32_t)(smem_addr)), "l"(gptr) : "memory")
#define CP_COMMIT() asm volatile("cp.async.commit_group;" ::: "memory")
#define CP_WAIT(n)  asm volatile("cp.async.wait_group %0;" :: "n"(n) : "memory")

__device__ __forceinline__ void ldsm4(uint32_t r[4], uint32_t addr) {
    asm volatile("ldmatrix.sync.aligned.m8n8.x4.shared.b16 {%0,%1,%2,%3}, [%4];"
                 : "=r"(r[0]), "=r"(r[1]), "=r"(r[2]), "=r"(r[3]) : "r"(addr));
}

__device__ __forceinline__ void mma16816h(float c[4], const uint32_t a[4],
                                          uint32_t b0, uint32_t b1) {
    asm volatile(
        "mma.sync.aligned.m16n8k16.row.col.f32.f16.f16.f32 "
        "{%0,%1,%2,%3}, {%4,%5,%6,%7}, {%8,%9}, {%0,%1,%2,%3};"
        : "+f"(c[0]), "+f"(c[1]), "+f"(c[2]), "+f"(c[3])
        : "r"(a[0]), "r"(a[1]), "r"(a[2]), "r"(a[3]), "r"(b0), "r"(b1));
}

__device__ __forceinline__ uint32_t packh2(float a, float b) {
    __half2 h = __floats2half2_rn(a, b);
    return *(uint32_t*)&h;
}

__device__ __forceinline__ void h_split(float x, __half& h, __half& l) {
    h = __float2half(x);
    l = __float2half(x - __half2float(h));
}

// ---------------------------------------------------------------------------
// Device scratch (all fp16)
// ---------------------------------------------------------------------------
__device__ __half g_lnvhi[MM*Dd];
__device__ __half g_lnvlo[MM*Dd];
__device__ __half g_lnkhi[MM*Dd];
__device__ __half g_lnklo[MM*Dd];
__device__ __half g_lnqhi[MM*Dd];
__device__ __half g_lnqlo[MM*Dd];
__device__ __half g_q16[MM*Dd];            // Q * D^-0.5
__device__ __half g_k16[MM*Dd];
__device__ __half g_v16[MM*Dd];
__device__ __half g_vt16[Bb*Hh*HSs*Ss];    // [(b*16+h)*64+e][s]
__device__ __half g_attnhi[MM*Dd];
__device__ __half g_attnlo[MM*Dd];
__device__ __half g_Wq16[Dd*Dd];           // [N,K]
__device__ __half g_Wk16[Dd*Dd];
__device__ __half g_Wv16[Dd*Dd];
__device__ __half g_Wp16[Dd*Dd];

// ---------------------------------------------------------------------------
// Weight reorder to [N,K] fp16. Wx[h,d,e] -> W[n=h*64+e][k=d]; Wp already [N,K].
// ---------------------------------------------------------------------------
__global__ void reorder_kernel(const float* __restrict__ Wq,
                               const float* __restrict__ Wk,
                               const float* __restrict__ Wv,
                               const float* __restrict__ Wp) {
    int idx = blockIdx.x * 256 + threadIdx.x;   // n*1024 + k
    int n = idx >> 10;
    int k = idx & 1023;
    int h = n >> 6;
    int e = n & 63;
    int src = h * (Dd * HSs) + k * HSs + e;
    g_Wq16[idx] = __float2half(Wq[src]);
    g_Wk16[idx] = __float2half(Wk[src]);
    g_Wv16[idx] = __float2half(Wv[src]);
    g_Wp16[idx] = __float2half(Wp[idx]);
}

// ---------------------------------------------------------------------------
// Fused layernorm for v,k,q  (grid: (MM, 3), 256 threads) + fp16 hi/lo split
// ---------------------------------------------------------------------------
__global__ __launch_bounds__(256) void ln_kernel(const float* __restrict__ v,
                                                 const float* __restrict__ k,
                                                 const float* __restrict__ q,
                                                 const float* __restrict__ g,
                                                 const float* __restrict__ b) {
    int row   = blockIdx.x;
    int which = blockIdx.y;
    const float* x;
    __half *yh, *yl;
    if (which == 0)      { x = v; yh = g_lnvhi; yl = g_lnvlo; }
    else if (which == 1) { x = k; yh = g_lnkhi; yl = g_lnklo; }
    else                 { x = q; yh = g_lnqhi; yl = g_lnqlo; }
    x  += (size_t)row * Dd;
    yh += (size_t)row * Dd;
    yl += (size_t)row * Dd;

    int t = threadIdx.x;
    float4 xv = ((const float4*)x)[t];
    float s1 = xv.x + xv.y + xv.z + xv.w;
    float s2 = xv.x*xv.x + xv.y*xv.y + xv.z*xv.z + xv.w*xv.w;
    #pragma unroll
    for (int off = 16; off; off >>= 1) {
        s1 += __shfl_xor_sync(0xffffffffu, s1, off);
        s2 += __shfl_xor_sync(0xffffffffu, s2, off);
    }
    __shared__ float w1[8], w2[8];
    __shared__ float smu, srs;
    int wid = t >> 5, lid = t & 31;
    if (lid == 0) { w1[wid] = s1; w2[wid] = s2; }
    __syncthreads();
    if (t == 0) {
        float t1 = 0.f, t2 = 0.f;
        #pragma unroll
        for (int i = 0; i < 8; i++) { t1 += w1[i]; t2 += w2[i]; }
        float mu  = t1 * (1.0f / Dd);
        float var = t2 * (1.0f / Dd) - mu * mu;
        smu = mu;
        srs = rsqrtf(var + 1e-5f);
    }
    __syncthreads();
    float mu = smu, rs = srs;
    float4 gv = ((const float4*)g)[t];
    float4 bv = ((const float4*)b)[t];
    float y0 = (xv.x - mu) * rs * gv.x + bv.x;
    float y1 = (xv.y - mu) * rs * gv.y + bv.y;
    float y2 = (xv.z - mu) * rs * gv.z + bv.z;
    float y3 = (xv.w - mu) * rs * gv.w + bv.w;
    __half h0, l0, h1, l1, h2, l2, h3, l3;
    h_split(y0, h0, l0); h_split(y1, h1, l1);
    h_split(y2, h2, l2); h_split(y3, h3, l3);
    __half2* yh2 = (__half2*)yh;
    __half2* yl2 = (__half2*)yl;
    yh2[2*t]   = __half2{h0, h1};
    yh2[2*t+1] = __half2{h2, h3};
    yl2[2*t]   = __half2{l0, l1};
    yl2[2*t+1] = __half2{l2, l3};
}

// ---------------------------------------------------------------------------
// fp16x2 mma.sync GEMM core: C = (Ahi+Alo) x B^T.
// CTA tile 128x128, BK=32, 8 warps (2x4), 2-stage cp.async.
// Smem stage: AH | AL | B, each 128 rows x 64B, swizzle chunk^((row>>1)&3).
// ---------------------------------------------------------------------------
#define GH_STAGE 24576
#define GH_SMEM  (2 * GH_STAGE)

__device__ __forceinline__ void gh_load(const __half* Ahi, const __half* Alo,
                                        const __half* Bm,
                                        int m0, int n0, int k0,
                                        uint32_t stage_base, int tid) {
    #pragma unroll
    for (int i = 0; i < 6; i++) {
        int gid = tid + i * 256;          // 0..1535
        int arr = gid >> 9;               // 0:AH 1:AL 2:B
        int idx = gid & 511;
        int row = idx >> 2;               // 0..127
        int c   = idx & 3;                // 16B chunk in 64B row
        uint32_t dst = stage_base + (uint32_t)arr * 8192u
                     + (uint32_t)row * 64u + (uint32_t)((c ^ ((row >> 1) & 3)) << 4);
        const __half* p = (arr == 0) ? Ahi : ((arr == 1) ? Alo : Bm);
        int g0 = (arr == 2) ? n0 : m0;
        CP_ASYNC16(dst, p + (size_t)(g0 + row) * Dd + k0 + c * 8);
    }
    CP_COMMIT();
}

// Mainloop shared by both GEMM kernels (acc produced in-place)
__device__ __forceinline__ void gh_mainloop(float acc[4][4][4],
                                            const __half* Ahi, const __half* Alo,
                                            const __half* Bm,
                                            int m0, int n0,
                                            uint32_t sb, int tid) {
    int wid  = tid >> 5;
    int lane = tid & 31;
    int wm = wid & 1;
    int wn = wid >> 1;
    int ti = lane >> 3, lr = lane & 7;

    gh_load(Ahi, Alo, Bm, m0, n0, 0, sb, tid);

    const int NC = Dd / 32;
    for (int c = 0; c < NC; c++) {
        uint32_t sBase = sb + (uint32_t)(c & 1) * GH_STAGE;
        if (c + 1 < NC) {
            gh_load(Ahi, Alo, Bm, m0, n0, (c + 1) * 32,
                    sb + (uint32_t)((c + 1) & 1) * GH_STAGE, tid);
            CP_WAIT(1);
        } else {
            CP_WAIT(0);
        }
        __syncthreads();

        #pragma unroll
        for (int kk = 0; kk < 32; kk += 16) {
            uint32_t aH[4][4], aL[4][4], bF[2][4];
            #pragma unroll
            for (int mt = 0; mt < 4; mt++) {
                int row = wm * 64 + mt * 16 + lr + (ti & 1) * 8;
                int ch  = (kk >> 3) + (ti >> 1);
                uint32_t ad = sBase + (uint32_t)row * 64u
                            + (uint32_t)((ch ^ ((row >> 1) & 3)) << 4);
                ldsm4(aH[mt], ad);
                ldsm4(aL[mt], ad + 8192);
            }
            #pragma unroll
            for (int ng = 0; ng < 2; ng++) {
                int row = wn * 32 + ng * 16 + lr + (ti >> 1) * 8;
                int ch  = (kk >> 3) + (ti & 1);
                uint32_t bd = sBase + 16384u + (uint32_t)row * 64u
                            + (uint32_t)((ch ^ ((row >> 1) & 3)) << 4);
                ldsm4(bF[ng], bd);
            }
            #pragma unroll
            for (int mt = 0; mt < 4; mt++)
                #pragma unroll
                for (int nt = 0; nt < 4; nt++) {
                    int ng = nt >> 1, hb = (nt & 1) * 2;
                    mma16816h(acc[mt][nt], aH[mt], bF[ng][hb], bF[ng][hb + 1]);
                    mma16816h(acc[mt][nt], aL[mt], bF[ng][hb], bF[ng][hb + 1]);
                }
        }
        __syncthreads();
    }
}

// QKV projections batched: z=0 Q(fp16, *D^-0.5), z=1 K(fp16), z=2 V(fp16)
__global__ __launch_bounds__(256, 1) void gemm_qkv_kernel() {
    extern __shared__ char smem[];
    uint32_t sb = smem_u32(smem);
    int tid = threadIdx.x;
    int z = blockIdx.z;
    int m0 = blockIdx.y * 128;
    int n0 = blockIdx.x * 128;

    const __half *Ahi, *Alo, *Bm;
    __half* dst;
    float sc;
    if (z == 0)      { Ahi = g_lnqhi; Alo = g_lnqlo; Bm = g_Wq16; dst = g_q16; sc = 0.03125f; }
    else if (z == 1) { Ahi = g_lnkhi; Alo = g_lnklo; Bm = g_Wk16; dst = g_k16; sc = 1.0f; }
    else             { Ahi = g_lnvhi; Alo = g_lnvlo; Bm = g_Wv16; dst = g_v16; sc = 1.0f; }

    float acc[4][4][4];
    #pragma unroll
    for (int i = 0; i < 4; i++)
        #pragma unroll
        for (int j = 0; j < 4; j++)
            #pragma unroll
            for (int r = 0; r < 4; r++) acc[i][j][r] = 0.f;

    gh_mainloop(acc, Ahi, Alo, Bm, m0, n0, sb, tid);

    int wid = tid >> 5, lane = tid & 31;
    int wm = wid & 1, wn = wid >> 1;
    #pragma unroll
    for (int mt = 0; mt < 4; mt++) {
        #pragma unroll
        for (int nt = 0; nt < 4; nt++) {
            int row = m0 + wm * 64 + mt * 16 + (lane >> 2);
            int col = n0 + wn * 32 + nt * 8 + (lane & 3) * 2;
            *(uint32_t*)(dst + (size_t)row * Dd + col) =
                packh2(acc[mt][nt][0] * sc, acc[mt][nt][1] * sc);
            *(uint32_t*)(dst + (size_t)(row + 8) * Dd + col) =
                packh2(acc[mt][nt][2] * sc, acc[mt][nt][3] * sc);
        }
    }
}

// Output projection: A = attn hi/lo, B = Wp16, C = fp32 out + bias
__global__ __launch_bounds__(256, 1) void gemm_out_kernel(float* __restrict__ C,
                                                          const float* __restrict__ bias) {
    extern __shared__ char smem[];
    uint32_t sb = smem_u32(smem);
    int tid = threadIdx.x;
    int m0 = blockIdx.y * 128;
    int n0 = blockIdx.x * 128;

    float acc[4][4][4];
    #pragma unroll
    for (int i = 0; i < 4; i++)
        #pragma unroll
        for (int j = 0; j < 4; j++)
            #pragma unroll
            for (int r = 0; r < 4; r++) acc[i][j][r] = 0.f;

    gh_mainloop(acc, g_attnhi, g_attnlo, g_Wp16, m0, n0, sb, tid);

    int wid = tid >> 5, lane = tid & 31;
    int wm = wid & 1, wn = wid >> 1;
    #pragma unroll
    for (int mt = 0; mt < 4; mt++) {
        #pragma unroll
        for (int nt = 0; nt < 4; nt++) {
            int row = m0 + wm * 64 + mt * 16 + (lane >> 2);
            int col = n0 + wn * 32 + nt * 8 + (lane & 3) * 2;
            float b0 = bias[col], b1 = bias[col + 1];
            *(float2*)(C + (size_t)row * Dd + col) =
                make_float2(acc[mt][nt][0] + b0, acc[mt][nt][1] + b1);
            *(float2*)(C + (size_t)(row + 8) * Dd + col) =
                make_float2(acc[mt][nt][2] + b0, acc[mt][nt][3] + b1);
        }
    }
}

// ---------------------------------------------------------------------------
// V transpose: g_v16 [token][h*64+e] -> g_vt16 [(b*16+h)*64+e][s]
// grid (S/64, B*H), 256 threads; smem tile 64x64 fp16, pitch 66 (conflict-free)
// ---------------------------------------------------------------------------
__global__ __launch_bounds__(256) void vt_kernel() {
    __shared__ __half ts[64][66];
    int s0 = blockIdx.x * 64;
    int bh = blockIdx.y;
    int b  = bh >> 4;
    int h  = bh & 15;
    int tid = threadIdx.x;
    #pragma unroll
    for (int i = 0; i < 16; i++) {
        int idx = tid + i * 256;
        int r = idx >> 6, e = idx & 63;
        ts[r][e] = g_v16[(size_t)(b * Ss + s0 + r) * Dd + h * HSs + e];
    }
    __syncthreads();
    #pragma unroll
    for (int i = 0; i < 16; i++) {
        int idx = tid + i * 256;
        int e = idx >> 6, t = idx & 63;
        g_vt16[((size_t)bh * HSs + e) * Ss + s0 + t] = ts[t][e];
    }
}

// ---------------------------------------------------------------------------
// Flash attention v2: fp16 mma.sync, causal, double-buffered K/V.
// BM=128, BN=64, 8 warps. smem: Q 16K | K0 8K | V0 8K | K1 8K | V1 8K = 48K
// grid: (S/128, B*H)
// ---------------------------------------------------------------------------
#define AT_Q  0
#define AT_KV 16384
#define AT2_SMEM 49152

__device__ __forceinline__ void at_load_kv(uint32_t sb, int s, int b, int bh,
                                           int k0, int tid) {
    uint32_t base = sb + AT_KV + (uint32_t)s * 16384u;
    #pragma unroll
    for (int i = 0; i < 2; i++) {
        int idx = tid + i * 256;
        int row = idx >> 3, c = idx & 7;
        uint32_t sw = (uint32_t)((c ^ (row & 7)) << 4);
        CP_ASYNC16(base + (uint32_t)row * 128u + sw,
                   g_k16 + (size_t)(b * Ss + k0 + row) * Dd + (bh & 15) * HSs + c * 8);
        CP_ASYNC16(base + 8192u + (uint32_t)row * 128u + sw,
                   g_vt16 + ((size_t)bh * HSs + row) * Ss + k0 + c * 8);
    }
    CP_COMMIT();
}

__global__ __launch_bounds__(256, 1) void attn2_kernel() {
    extern __shared__ char smem[];
    uint32_t sb = smem_u32(smem);
    int qb = blockIdx.x;
    int bh = blockIdx.y;
    int b  = bh >> 4;
    int h  = bh & 15;
    int q0 = qb * 128;

    int tid  = threadIdx.x;
    int wid  = tid >> 5;
    int lane = tid & 31;
    int lr = lane & 7, ti = lane >> 3;

    // Load Q tile (128 x 64 fp16)
    #pragma unroll
    for (int i = 0; i < 4; i++) {
        int idx = tid + i * 256;
        int row = idx >> 3, c = idx & 7;
        uint32_t dst = sb + AT_Q + (uint32_t)row * 128u + (uint32_t)((c ^ (row & 7)) << 4);
        CP_ASYNC16(dst, g_q16 + (size_t)(b * Ss + q0 + row) * Dd + h * HSs + c * 8);
    }
    CP_COMMIT();
    at_load_kv(sb, 0, b, bh, 0, tid);

    float m0 = -1e30f, m1 = -1e30f, l0 = 0.f, l1 = 0.f;
    float O[8][4];
    #pragma unroll
    for (int f = 0; f < 8; f++)
        #pragma unroll
        for (int r = 0; r < 4; r++) O[f][r] = 0.f;

    int NB = 2 * qb + 2;
    for (int kb = 0; kb < NB; kb++) {
        int s = kb & 1;
        int k0 = kb * 64;
        CP_WAIT(0);
        __syncthreads();
        if (kb + 1 < NB) at_load_kv(sb, s ^ 1, b, bh, (kb + 1) * 64, tid);

        uint32_t sK = sb + AT_KV + (uint32_t)s * 16384u;
        uint32_t sV = sK + 8192u;

        // S = Q K^T
        uint32_t aQ[4][4];
        #pragma unroll
        for (int ks = 0; ks < 4; ks++) {
            int row = wid * 16 + lr + (ti & 1) * 8;
            int ch  = 2 * ks + (ti >> 1);
            ldsm4(aQ[ks], sb + AT_Q + (uint32_t)row * 128u
                          + (uint32_t)((ch ^ (row & 7)) << 4));
        }
        float S[8][4];
        #pragma unroll
        for (int f = 0; f < 8; f++)
            #pragma unroll
            for (int r = 0; r < 4; r++) S[f][r] = 0.f;

        #pragma unroll
        for (int nt = 0; nt < 4; nt++) {
            int krow = nt * 16 + lr + (ti >> 1) * 8;
            #pragma unroll
            for (int ks = 0; ks < 4; ks++) {
                int ch = 2 * ks + (ti & 1);
                uint32_t bK[4];
                ldsm4(bK, sK + (uint32_t)krow * 128u
                          + (uint32_t)((ch ^ (krow & 7)) << 4));
                mma16816h(S[2 * nt],     aQ[ks], bK[0], bK[1]);
                mma16816h(S[2 * nt + 1], aQ[ks], bK[2], bK[3]);
            }
        }

        // causal mask (diagonal band only)
        if (kb >= 2 * qb) {
            int r0 = q0 + wid * 16 + (lane >> 2);
            #pragma unroll
            for (int f = 0; f < 8; f++) {
                int kg = k0 + f * 8 + 2 * (lane & 3);
                if (kg     > r0)     S[f][0] = -1e30f;
                if (kg + 1 > r0)     S[f][1] = -1e30f;
                if (kg     > r0 + 8) S[f][2] = -1e30f;
                if (kg + 1 > r0 + 8) S[f][3] = -1e30f;
            }
        }

        // online softmax
        float mx0 = -1e30f, mx1 = -1e30f;
        #pragma unroll
        for (int f = 0; f < 8; f++) {
            mx0 = fmaxf(mx0, fmaxf(S[f][0], S[f][1]));
            mx1 = fmaxf(mx1, fmaxf(S[f][2], S[f][3]));
        }
        mx0 = fmaxf(mx0, __shfl_xor_sync(0xffffffffu, mx0, 1));
        mx0 = fmaxf(mx0, __shfl_xor_sync(0xffffffffu, mx0, 2));
        mx1 = fmaxf(mx1, __shfl_xor_sync(0xffffffffu, mx1, 1));
        mx1 = fmaxf(mx1, __shfl_xor_sync(0xffffffffu, mx1, 2));
        float mn0 = fmaxf(m0, mx0), mn1 = fmaxf(m1, mx1);
        float al0 = __expf(m0 - mn0), al1 = __expf(m1 - mn1);
        float rs0 = 0.f, rs1 = 0.f;
        #pragma unroll
        for (int f = 0; f < 8; f++) {
            S[f][0] = __expf(S[f][0] - mn0);
            S[f][1] = __expf(S[f][1] - mn0);
            S[f][2] = __expf(S[f][2] - mn1);
            S[f][3] = __expf(S[f][3] - mn1);
            rs0 += S[f][0] + S[f][1];
            rs1 += S[f][2] + S[f][3];
        }
        rs0 += __shfl_xor_sync(0xffffffffu, rs0, 1);
        rs0 += __shfl_xor_sync(0xffffffffu, rs0, 2);
        rs1 += __shfl_xor_sync(0xffffffffu, rs1, 1);
        rs1 += __shfl_xor_sync(0xffffffffu, rs1, 2);
        l0 = l0 * al0 + rs0;
        l1 = l1 * al1 + rs1;
        m0 = mn0; m1 = mn1;
        #pragma unroll
        for (int f = 0; f < 8; f++) {
            O[f][0] *= al0; O[f][1] *= al0;
            O[f][2] *= al1; O[f][3] *= al1;
        }

        // P fragments (C-frag -> A-frag identity)
        uint32_t aP[4][4];
        #pragma unroll
        for (int f2 = 0; f2 < 4; f2++) {
            aP[f2][0] = packh2(S[2 * f2][0],     S[2 * f2][1]);
            aP[f2][1] = packh2(S[2 * f2][2],     S[2 * f2][3]);
            aP[f2][2] = packh2(S[2 * f2 + 1][0], S[2 * f2 + 1][1]);
            aP[f2][3] = packh2(S[2 * f2 + 1][2], S[2 * f2 + 1][3]);
        }

        // O += P V
        #pragma unroll
        for (int nt = 0; nt < 4; nt++) {
            int vrow = nt * 16 + lr + (ti >> 1) * 8;
            #pragma unroll
            for (int f2 = 0; f2 < 4; f2++) {
                int ch = 2 * f2 + (ti & 1);
                uint32_t bV[4];
                ldsm4(bV, sV + (uint32_t)vrow * 128u
                          + (uint32_t)((ch ^ (vrow & 7)) << 4));
                mma16816h(O[2 * nt],     aP[f2], bV[0], bV[1]);
                mma16816h(O[2 * nt + 1], aP[f2], bV[2], bV[3]);
            }
        }
    }

    // Epilogue: normalize + fp16 hi/lo split
    float inv0 = 1.0f / l0, inv1 = 1.0f / l1;
    int row0 = q0 + wid * 16 + (lane >> 2);
    #pragma unroll
    for (int f = 0; f < 8; f++) {
        int col = h * HSs + f * 8 + 2 * (lane & 3);
        float v00 = O[f][0] * inv0, v01 = O[f][1] * inv0;
        float v10 = O[f][2] * inv1, v11 = O[f][3] * inv1;
        __half h00, l00, h01, l01, h10, l10, h11, l11;
        h_split(v00, h00, l00); h_split(v01, h01, l01);
        h_split(v10, h10, l10); h_split(v11, h11, l11);
        size_t o0 = (size_t)(b * Ss + row0) * Dd + col;
        size_t o1 = (size_t)(b * Ss + row0 + 8) * Dd + col;
        *(__half2*)(g_attnhi + o0) = __half2{h00, h01};
        *(__half2*)(g_attnlo + o0) = __half2{l00, l01};
        *(__half2*)(g_attnhi + o1) = __half2{h10, h11};
        *(__half2*)(g_attnlo + o1) = __half2{l10, l11};
    }
}

// ---------------------------------------------------------------------------
// Host launch (graph-capturable: kernels only)
// ---------------------------------------------------------------------------
extern "C" void kernel_launch(void* const* d_in, const int* in_sizes, int n_in,
                              void* d_out, int out_size) {
    const float* v   = (const float*)d_in[0];
    const float* k   = (const float*)d_in[1];
    const float* q   = (const float*)d_in[2];
    const float* lng = (const float*)d_in[4];
    const float* lnb = (const float*)d_in[5];
    const float* Wq  = (const float*)d_in[6];
    const float* Wk  = (const float*)d_in[7];
    const float* Wv  = (const float*)d_in[8];
    const float* Wp  = (const float*)d_in[9];
    const float* bp  = (const float*)d_in[10];
    float* out = (float*)d_out;

    cudaFuncSetAttribute(gemm_qkv_kernel,
                         cudaFuncAttributeMaxDynamicSharedMemorySize, GH_SMEM);
    cudaFuncSetAttribute(gemm_out_kernel,
                         cudaFuncAttributeMaxDynamicSharedMemorySize, GH_SMEM);
    cudaFuncSetAttribute(attn2_kernel,
                         cudaFuncAttributeMaxDynamicSharedMemorySize, AT2_SMEM);

    reorder_kernel<<<(Dd * Dd) / 256, 256>>>(Wq, Wk, Wv, Wp);
    ln_kernel<<<dim3(MM, 3), 256>>>(v, k, q, lng, lnb);
    gemm_qkv_kernel<<<dim3(Dd / 128, MM / 128, 3), 256, GH_SMEM>>>();
    vt_kernel<<<dim3(Ss / 64, Bb * Hh), 256>>>();
    attn2_kernel<<<dim3(Ss / 128, Bb * Hh), 256, AT2_SMEM>>>();
    gemm_out_kernel<<<dim3(Dd / 128, MM / 128), 256, GH_SMEM>>>(out, bp);
}

// round 11
// speedup vs baseline: 4.3080x; 1.0067x over previous
#include <cuda_runtime.h>
#include <cuda_fp16.h>
#include <cstdint>
#include <math.h>

// Problem constants
#define Bb  4
#define Ss  2048
#define Dd  1024
#define Hh  16
#define HSs 64
#define MM  (Bb*Ss)   // 8192 rows

// ---------------------------------------------------------------------------
// PTX helpers (baseline PTX only — harness emits compute_103, no 'a' features)
// ---------------------------------------------------------------------------
__device__ __forceinline__ uint32_t smem_u32(const void* p) {
    uint32_t a;
    asm("{ .reg .u64 t; cvta.to.shared.u64 t, %1; cvt.u32.u64 %0, t; }"
        : "=r"(a) : "l"(p));
    return a;
}

#define CP_ASYNC16(smem_addr, gptr) \
    asm volatile("cp.async.cg.shared.global [%0], [%1], 16;" \
                 :: "r"((uint32_t)(smem_addr)), "l"(gptr) : "memory")
#define CP_COMMIT() asm volatile("cp.async.commit_group;" ::: "memory")
#define CP_WAIT(n)  asm volatile("cp.async.wait_group %0;" :: "n"(n) : "memory")

__device__ __forceinline__ void ldsm4(uint32_t r[4], uint32_t addr) {
    asm volatile("ldmatrix.sync.aligned.m8n8.x4.shared.b16 {%0,%1,%2,%3}, [%4];"
                 : "=r"(r[0]), "=r"(r[1]), "=r"(r[2]), "=r"(r[3]) : "r"(addr));
}

__device__ __forceinline__ void mma16816h(float c[4], const uint32_t a[4],
                                          uint32_t b0, uint32_t b1) {
    asm volatile(
        "mma.sync.aligned.m16n8k16.row.col.f32.f16.f16.f32 "
        "{%0,%1,%2,%3}, {%4,%5,%6,%7}, {%8,%9}, {%0,%1,%2,%3};"
        : "+f"(c[0]), "+f"(c[1]), "+f"(c[2]), "+f"(c[3])
        : "r"(a[0]), "r"(a[1]), "r"(a[2]), "r"(a[3]), "r"(b0), "r"(b1));
}

__device__ __forceinline__ uint32_t packh2(float a, float b) {
    __half2 h = __floats2half2_rn(a, b);
    return *(uint32_t*)&h;
}

__device__ __forceinline__ void h_split(float x, __half& h, __half& l) {
    h = __float2half(x);
    l = __float2half(x - __half2float(h));
}

// ---------------------------------------------------------------------------
// Device scratch (all fp16)
// ---------------------------------------------------------------------------
__device__ __half g_lnvhi[MM*Dd];
__device__ __half g_lnvlo[MM*Dd];
__device__ __half g_lnkhi[MM*Dd];
__device__ __half g_lnklo[MM*Dd];
__device__ __half g_lnqhi[MM*Dd];
__device__ __half g_lnqlo[MM*Dd];
__device__ __half g_q16[MM*Dd];            // Q * D^-0.5
__device__ __half g_k16[MM*Dd];
__device__ __half g_v16[MM*Dd];
__device__ __half g_vt16[Bb*Hh*HSs*Ss];    // [(b*16+h)*64+e][s]
__device__ __half g_attnhi[MM*Dd];
__device__ __half g_attnlo[MM*Dd];
__device__ __half g_Wq16[Dd*Dd];           // [N,K]
__device__ __half g_Wk16[Dd*Dd];
__device__ __half g_Wv16[Dd*Dd];
__device__ __half g_Wp16[Dd*Dd];

// ---------------------------------------------------------------------------
// Weight reorder to [N,K] fp16. Wx[h,d,e] -> W[n=h*64+e][k=d]; Wp already [N,K].
// ---------------------------------------------------------------------------
__global__ void reorder_kernel(const float* __restrict__ Wq,
                               const float* __restrict__ Wk,
                               const float* __restrict__ Wv,
                               const float* __restrict__ Wp) {
    int idx = blockIdx.x * 256 + threadIdx.x;   // n*1024 + k
    int n = idx >> 10;
    int k = idx & 1023;
    int h = n >> 6;
    int e = n & 63;
    int src = h * (Dd * HSs) + k * HSs + e;
    g_Wq16[idx] = __float2half(Wq[src]);
    g_Wk16[idx] = __float2half(Wk[src]);
    g_Wv16[idx] = __float2half(Wv[src]);
    g_Wp16[idx] = __float2half(Wp[idx]);
}

// ---------------------------------------------------------------------------
// Fused layernorm for v,k,q  (grid: (MM, 3), 256 threads) + fp16 hi/lo split
// ---------------------------------------------------------------------------
__global__ __launch_bounds__(256) void ln_kernel(const float* __restrict__ v,
                                                 const float* __restrict__ k,
                                                 const float* __restrict__ q,
                                                 const float* __restrict__ g,
                                                 const float* __restrict__ b) {
    int row   = blockIdx.x;
    int which = blockIdx.y;
    const float* x;
    __half *yh, *yl;
    if (which == 0)      { x = v; yh = g_lnvhi; yl = g_lnvlo; }
    else if (which == 1) { x = k; yh = g_lnkhi; yl = g_lnklo; }
    else                 { x = q; yh = g_lnqhi; yl = g_lnqlo; }
    x  += (size_t)row * Dd;
    yh += (size_t)row * Dd;
    yl += (size_t)row * Dd;

    int t = threadIdx.x;
    float4 xv = ((const float4*)x)[t];
    float s1 = xv.x + xv.y + xv.z + xv.w;
    float s2 = xv.x*xv.x + xv.y*xv.y + xv.z*xv.z + xv.w*xv.w;
    #pragma unroll
    for (int off = 16; off; off >>= 1) {
        s1 += __shfl_xor_sync(0xffffffffu, s1, off);
        s2 += __shfl_xor_sync(0xffffffffu, s2, off);
    }
    __shared__ float w1[8], w2[8];
    __shared__ float smu, srs;
    int wid = t >> 5, lid = t & 31;
    if (lid == 0) { w1[wid] = s1; w2[wid] = s2; }
    __syncthreads();
    if (t == 0) {
        float t1 = 0.f, t2 = 0.f;
        #pragma unroll
        for (int i = 0; i < 8; i++) { t1 += w1[i]; t2 += w2[i]; }
        float mu  = t1 * (1.0f / Dd);
        float var = t2 * (1.0f / Dd) - mu * mu;
        smu = mu;
        srs = rsqrtf(var + 1e-5f);
    }
    __syncthreads();
    float mu = smu, rs = srs;
    float4 gv = ((const float4*)g)[t];
    float4 bv = ((const float4*)b)[t];
    float y0 = (xv.x - mu) * rs * gv.x + bv.x;
    float y1 = (xv.y - mu) * rs * gv.y + bv.y;
    float y2 = (xv.z - mu) * rs * gv.z + bv.z;
    float y3 = (xv.w - mu) * rs * gv.w + bv.w;
    __half h0, l0, h1, l1, h2, l2, h3, l3;
    h_split(y0, h0, l0); h_split(y1, h1, l1);
    h_split(y2, h2, l2); h_split(y3, h3, l3);
    __half2* yh2 = (__half2*)yh;
    __half2* yl2 = (__half2*)yl;
    yh2[2*t]   = __half2{h0, h1};
    yh2[2*t+1] = __half2{h2, h3};
    yl2[2*t]   = __half2{l0, l1};
    yl2[2*t+1] = __half2{l2, l3};
}

// ---------------------------------------------------------------------------
// fp16x2 mma.sync GEMM core: C = (Ahi+Alo) x B^T.
// CTA tile 128x128, BK=32, 8 warps (2x4), 3-stage cp.async, 1 barrier/chunk.
// Smem stage: AH | AL | B, each 128 rows x 64B, swizzle chunk^((row>>1)&3).
// ---------------------------------------------------------------------------
#define GH_STAGE 24576
#define GH_SMEM  (3 * GH_STAGE)

__device__ __forceinline__ void gh_load(const __half* Ahi, const __half* Alo,
                                        const __half* Bm,
                                        int m0, int n0, int k0,
                                        uint32_t stage_base, int tid) {
    #pragma unroll
    for (int i = 0; i < 6; i++) {
        int gid = tid + i * 256;          // 0..1535
        int arr = gid >> 9;               // 0:AH 1:AL 2:B
        int idx = gid & 511;
        int row = idx >> 2;               // 0..127
        int c   = idx & 3;                // 16B chunk in 64B row
        uint32_t dst = stage_base + (uint32_t)arr * 8192u
                     + (uint32_t)row * 64u + (uint32_t)((c ^ ((row >> 1) & 3)) << 4);
        const __half* p = (arr == 0) ? Ahi : ((arr == 1) ? Alo : Bm);
        int g0 = (arr == 2) ? n0 : m0;
        CP_ASYNC16(dst, p + (size_t)(g0 + row) * Dd + k0 + c * 8);
    }
    CP_COMMIT();
}

// Mainloop shared by both GEMM kernels (acc produced in-place).
// 3-stage pipeline: barrier at iter c certifies compute c-1 done, so
// stage (c+2)%3 == (c-1)%3 is free for the c+2 load.
__device__ __forceinline__ void gh_mainloop(float acc[4][4][4],
                                            const __half* Ahi, const __half* Alo,
                                            const __half* Bm,
                                            int m0, int n0,
                                            uint32_t sb, int tid) {
    int wid  = tid >> 5;
    int lane = tid & 31;
    int wm = wid & 1;
    int wn = wid >> 1;
    int ti = lane >> 3, lr = lane & 7;

    const int NC = Dd / 32;   // 32 chunks
    gh_load(Ahi, Alo, Bm, m0, n0, 0, sb, tid);
    gh_load(Ahi, Alo, Bm, m0, n0, 32, sb + GH_STAGE, tid);

    int st = 0;          // stage of chunk c
    int stN = 2;         // stage for chunk c+2
    for (int c = 0; c < NC; c++) {
        if (c + 1 < NC) { CP_WAIT(1); } else { CP_WAIT(0); }
        __syncthreads();
        if (c + 2 < NC)
            gh_load(Ahi, Alo, Bm, m0, n0, (c + 2) * 32,
                    sb + (uint32_t)stN * GH_STAGE, tid);
        uint32_t sBase = sb + (uint32_t)st * GH_STAGE;
        st  = (st  == 2) ? 0 : st + 1;
        stN = (stN == 2) ? 0 : stN + 1;

        #pragma unroll
        for (int kk = 0; kk < 32; kk += 16) {
            uint32_t aH[4][4], aL[4][4], bF[2][4];
            #pragma unroll
            for (int mt = 0; mt < 4; mt++) {
                int row = wm * 64 + mt * 16 + lr + (ti & 1) * 8;
                int ch  = (kk >> 3) + (ti >> 1);
                uint32_t ad = sBase + (uint32_t)row * 64u
                            + (uint32_t)((ch ^ ((row >> 1) & 3)) << 4);
                ldsm4(aH[mt], ad);
                ldsm4(aL[mt], ad + 8192);
            }
            #pragma unroll
            for (int ng = 0; ng < 2; ng++) {
                int row = wn * 32 + ng * 16 + lr + (ti >> 1) * 8;
                int ch  = (kk >> 3) + (ti & 1);
                uint32_t bd = sBase + 16384u + (uint32_t)row * 64u
                            + (uint32_t)((ch ^ ((row >> 1) & 3)) << 4);
                ldsm4(bF[ng], bd);
            }
            #pragma unroll
            for (int mt = 0; mt < 4; mt++)
                #pragma unroll
                for (int nt = 0; nt < 4; nt++) {
                    int ng = nt >> 1, hb = (nt & 1) * 2;
                    mma16816h(acc[mt][nt], aH[mt], bF[ng][hb], bF[ng][hb + 1]);
                    mma16816h(acc[mt][nt], aL[mt], bF[ng][hb], bF[ng][hb + 1]);
                }
        }
    }
    __syncthreads();
}

// QKV projections batched: z=0 Q(fp16, *D^-0.5), z=1 K(fp16), z=2 V(fp16)
__global__ __launch_bounds__(256, 1) void gemm_qkv_kernel() {
    extern __shared__ char smem[];
    uint32_t sb = smem_u32(smem);
    int tid = threadIdx.x;
    int z = blockIdx.z;
    int m0 = blockIdx.y * 128;
    int n0 = blockIdx.x * 128;

    const __half *Ahi, *Alo, *Bm;
    __half* dst;
    float sc;
    if (z == 0)      { Ahi = g_lnqhi; Alo = g_lnqlo; Bm = g_Wq16; dst = g_q16; sc = 0.03125f; }
    else if (z == 1) { Ahi = g_lnkhi; Alo = g_lnklo; Bm = g_Wk16; dst = g_k16; sc = 1.0f; }
    else             { Ahi = g_lnvhi; Alo = g_lnvlo; Bm = g_Wv16; dst = g_v16; sc = 1.0f; }

    float acc[4][4][4];
    #pragma unroll
    for (int i = 0; i < 4; i++)
        #pragma unroll
        for (int j = 0; j < 4; j++)
            #pragma unroll
            for (int r = 0; r < 4; r++) acc[i][j][r] = 0.f;

    gh_mainloop(acc, Ahi, Alo, Bm, m0, n0, sb, tid);

    int wid = tid >> 5, lane = tid & 31;
    int wm = wid & 1, wn = wid >> 1;
    #pragma unroll
    for (int mt = 0; mt < 4; mt++) {
        #pragma unroll
        for (int nt = 0; nt < 4; nt++) {
            int row = m0 + wm * 64 + mt * 16 + (lane >> 2);
            int col = n0 + wn * 32 + nt * 8 + (lane & 3) * 2;
            *(uint32_t*)(dst + (size_t)row * Dd + col) =
                packh2(acc[mt][nt][0] * sc, acc[mt][nt][1] * sc);
            *(uint32_t*)(dst + (size_t)(row + 8) * Dd + col) =
                packh2(acc[mt][nt][2] * sc, acc[mt][nt][3] * sc);
        }
    }
}

// Output projection: A = attn hi/lo, B = Wp16, C = fp32 out + bias
__global__ __launch_bounds__(256, 1) void gemm_out_kernel(float* __restrict__ C,
                                                          const float* __restrict__ bias) {
    extern __shared__ char smem[];
    uint32_t sb = smem_u32(smem);
    int tid = threadIdx.x;
    int m0 = blockIdx.y * 128;
    int n0 = blockIdx.x * 128;

    float acc[4][4][4];
    #pragma unroll
    for (int i = 0; i < 4; i++)
        #pragma unroll
        for (int j = 0; j < 4; j++)
            #pragma unroll
            for (int r = 0; r < 4; r++) acc[i][j][r] = 0.f;

    gh_mainloop(acc, g_attnhi, g_attnlo, g_Wp16, m0, n0, sb, tid);

    int wid = tid >> 5, lane = tid & 31;
    int wm = wid & 1, wn = wid >> 1;
    #pragma unroll
    for (int mt = 0; mt < 4; mt++) {
        #pragma unroll
        for (int nt = 0; nt < 4; nt++) {
            int row = m0 + wm * 64 + mt * 16 + (lane >> 2);
            int col = n0 + wn * 32 + nt * 8 + (lane & 3) * 2;
            float b0 = bias[col], b1 = bias[col + 1];
            *(float2*)(C + (size_t)row * Dd + col) =
                make_float2(acc[mt][nt][0] + b0, acc[mt][nt][1] + b1);
            *(float2*)(C + (size_t)(row + 8) * Dd + col) =
                make_float2(acc[mt][nt][2] + b0, acc[mt][nt][3] + b1);
        }
    }
}

// ---------------------------------------------------------------------------
// V transpose: g_v16 [token][h*64+e] -> g_vt16 [(b*16+h)*64+e][s]
// grid (S/64, B*H), 256 threads; smem tile 64x64 fp16, pitch 66 (conflict-free)
// ---------------------------------------------------------------------------
__global__ __launch_bounds__(256) void vt_kernel() {
    __shared__ __half ts[64][66];
    int s0 = blockIdx.x * 64;
    int bh = blockIdx.y;
    int b  = bh >> 4;
    int h  = bh & 15;
    int tid = threadIdx.x;
    #pragma unroll
    for (int i = 0; i < 16; i++) {
        int idx = tid + i * 256;
        int r = idx >> 6, e = idx & 63;
        ts[r][e] = g_v16[(size_t)(b * Ss + s0 + r) * Dd + h * HSs + e];
    }
    __syncthreads();
    #pragma unroll
    for (int i = 0; i < 16; i++) {
        int idx = tid + i * 256;
        int e = idx >> 6, t = idx & 63;
        g_vt16[((size_t)bh * HSs + e) * Ss + s0 + t] = ts[t][e];
    }
}

// ---------------------------------------------------------------------------
// Flash attention v2: fp16 mma.sync, causal, double-buffered K/V.
// BM=128, BN=64, 8 warps. smem: Q 16K | K0 8K | V0 8K | K1 8K | V1 8K = 48K
// grid: (S/128, B*H)
// ---------------------------------------------------------------------------
#define AT_Q  0
#define AT_KV 16384
#define AT2_SMEM 49152

__device__ __forceinline__ void at_load_kv(uint32_t sb, int s, int b, int bh,
                                           int k0, int tid) {
    uint32_t base = sb + AT_KV + (uint32_t)s * 16384u;
    #pragma unroll
    for (int i = 0; i < 2; i++) {
        int idx = tid + i * 256;
        int row = idx >> 3, c = idx & 7;
        uint32_t sw = (uint32_t)((c ^ (row & 7)) << 4);
        CP_ASYNC16(base + (uint32_t)row * 128u + sw,
                   g_k16 + (size_t)(b * Ss + k0 + row) * Dd + (bh & 15) * HSs + c * 8);
        CP_ASYNC16(base + 8192u + (uint32_t)row * 128u + sw,
                   g_vt16 + ((size_t)bh * HSs + row) * Ss + k0 + c * 8);
    }
    CP_COMMIT();
}

__global__ __launch_bounds__(256, 1) void attn2_kernel() {
    extern __shared__ char smem[];
    uint32_t sb = smem_u32(smem);
    int qb = blockIdx.x;
    int bh = blockIdx.y;
    int b  = bh >> 4;
    int h  = bh & 15;
    int q0 = qb * 128;

    int tid  = threadIdx.x;
    int wid  = tid >> 5;
    int lane = tid & 31;
    int lr = lane & 7, ti = lane >> 3;

    // Load Q tile (128 x 64 fp16)
    #pragma unroll
    for (int i = 0; i < 4; i++) {
        int idx = tid + i * 256;
        int row = idx >> 3, c = idx & 7;
        uint32_t dst = sb + AT_Q + (uint32_t)row * 128u + (uint32_t)((c ^ (row & 7)) << 4);
        CP_ASYNC16(dst, g_q16 + (size_t)(b * Ss + q0 + row) * Dd + h * HSs + c * 8);
    }
    CP_COMMIT();
    at_load_kv(sb, 0, b, bh, 0, tid);

    float m0 = -1e30f, m1 = -1e30f, l0 = 0.f, l1 = 0.f;
    float O[8][4];
    #pragma unroll
    for (int f = 0; f < 8; f++)
        #pragma unroll
        for (int r = 0; r < 4; r++) O[f][r] = 0.f;

    int NB = 2 * qb + 2;
    for (int kb = 0; kb < NB; kb++) {
        int s = kb & 1;
        int k0 = kb * 64;
        CP_WAIT(0);
        __syncthreads();
        if (kb + 1 < NB) at_load_kv(sb, s ^ 1, b, bh, (kb + 1) * 64, tid);

        uint32_t sK = sb + AT_KV + (uint32_t)s * 16384u;
        uint32_t sV = sK + 8192u;

        // S = Q K^T
        uint32_t aQ[4][4];
        #pragma unroll
        for (int ks = 0; ks < 4; ks++) {
            int row = wid * 16 + lr + (ti & 1) * 8;
            int ch  = 2 * ks + (ti >> 1);
            ldsm4(aQ[ks], sb + AT_Q + (uint32_t)row * 128u
                          + (uint32_t)((ch ^ (row & 7)) << 4));
        }
        float S[8][4];
        #pragma unroll
        for (int f = 0; f < 8; f++)
            #pragma unroll
            for (int r = 0; r < 4; r++) S[f][r] = 0.f;

        #pragma unroll
        for (int nt = 0; nt < 4; nt++) {
            int krow = nt * 16 + lr + (ti >> 1) * 8;
            #pragma unroll
            for (int ks = 0; ks < 4; ks++) {
                int ch = 2 * ks + (ti & 1);
                uint32_t bK[4];
                ldsm4(bK, sK + (uint32_t)krow * 128u
                          + (uint32_t)((ch ^ (krow & 7)) << 4));
                mma16816h(S[2 * nt],     aQ[ks], bK[0], bK[1]);
                mma16816h(S[2 * nt + 1], aQ[ks], bK[2], bK[3]);
            }
        }

        // causal mask (diagonal band only)
        if (kb >= 2 * qb) {
            int r0 = q0 + wid * 16 + (lane >> 2);
            #pragma unroll
            for (int f = 0; f < 8; f++) {
                int kg = k0 + f * 8 + 2 * (lane & 3);
                if (kg     > r0)     S[f][0] = -1e30f;
                if (kg + 1 > r0)     S[f][1] = -1e30f;
                if (kg     > r0 + 8) S[f][2] = -1e30f;
                if (kg + 1 > r0 + 8) S[f][3] = -1e30f;
            }
        }

        // online softmax
        float mx0 = -1e30f, mx1 = -1e30f;
        #pragma unroll
        for (int f = 0; f < 8; f++) {
            mx0 = fmaxf(mx0, fmaxf(S[f][0], S[f][1]));
            mx1 = fmaxf(mx1, fmaxf(S[f][2], S[f][3]));
        }
        mx0 = fmaxf(mx0, __shfl_xor_sync(0xffffffffu, mx0, 1));
        mx0 = fmaxf(mx0, __shfl_xor_sync(0xffffffffu, mx0, 2));
        mx1 = fmaxf(mx1, __shfl_xor_sync(0xffffffffu, mx1, 1));
        mx1 = fmaxf(mx1, __shfl_xor_sync(0xffffffffu, mx1, 2));
        float mn0 = fmaxf(m0, mx0), mn1 = fmaxf(m1, mx1);
        float al0 = __expf(m0 - mn0), al1 = __expf(m1 - mn1);
        float rs0 = 0.f, rs1 = 0.f;
        #pragma unroll
        for (int f = 0; f < 8; f++) {
            S[f][0] = __expf(S[f][0] - mn0);
            S[f][1] = __expf(S[f][1] - mn0);
            S[f][2] = __expf(S[f][2] - mn1);
            S[f][3] = __expf(S[f][3] - mn1);
            rs0 += S[f][0] + S[f][1];
            rs1 += S[f][2] + S[f][3];
        }
        rs0 += __shfl_xor_sync(0xffffffffu, rs0, 1);
        rs0 += __shfl_xor_sync(0xffffffffu, rs0, 2);
        rs1 += __shfl_xor_sync(0xffffffffu, rs1, 1);
        rs1 += __shfl_xor_sync(0xffffffffu, rs1, 2);
        l0 = l0 * al0 + rs0;
        l1 = l1 * al1 + rs1;
        m0 = mn0; m1 = mn1;
        #pragma unroll
        for (int f = 0; f < 8; f++) {
            O[f][0] *= al0; O[f][1] *= al0;
            O[f][2] *= al1; O[f][3] *= al1;
        }

        // P fragments (C-frag -> A-frag identity)
        uint32_t aP[4][4];
        #pragma unroll
        for (int f2 = 0; f2 < 4; f2++) {
            aP[f2][0] = packh2(S[2 * f2][0],     S[2 * f2][1]);
            aP[f2][1] = packh2(S[2 * f2][2],     S[2 * f2][3]);
            aP[f2][2] = packh2(S[2 * f2 + 1][0], S[2 * f2 + 1][1]);
            aP[f2][3] = packh2(S[2 * f2 + 1][2], S[2 * f2 + 1][3]);
        }

        // O += P V
        #pragma unroll
        for (int nt = 0; nt < 4; nt++) {
            int vrow = nt * 16 + lr + (ti >> 1) * 8;
            #pragma unroll
            for (int f2 = 0; f2 < 4; f2++) {
                int ch = 2 * f2 + (ti & 1);
                uint32_t bV[4];
                ldsm4(bV, sV + (uint32_t)vrow * 128u
                          + (uint32_t)((ch ^ (vrow & 7)) << 4));
                mma16816h(O[2 * nt],     aP[f2], bV[0], bV[1]);
                mma16816h(O[2 * nt + 1], aP[f2], bV[2], bV[3]);
            }
        }
    }

    // Epilogue: normalize + fp16 hi/lo split
    float inv0 = 1.0f / l0, inv1 = 1.0f / l1;
    int row0 = q0 + wid * 16 + (lane >> 2);
    #pragma unroll
    for (int f = 0; f < 8; f++) {
        int col = h * HSs + f * 8 + 2 * (lane & 3);
        float v00 = O[f][0] * inv0, v01 = O[f][1] * inv0;
        float v10 = O[f][2] * inv1, v11 = O[f][3] * inv1;
        __half h00, l00, h01, l01, h10, l10, h11, l11;
        h_split(v00, h00, l00); h_split(v01, h01, l01);
        h_split(v10, h10, l10); h_split(v11, h11, l11);
        size_t o0 = (size_t)(b * Ss + row0) * Dd + col;
        size_t o1 = (size_t)(b * Ss + row0 + 8) * Dd + col;
        *(__half2*)(g_attnhi + o0) = __half2{h00, h01};
        *(__half2*)(g_attnlo + o0) = __half2{l00, l01};
        *(__half2*)(g_attnhi + o1) = __half2{h10, h11};
        *(__half2*)(g_attnlo + o1) = __half2{l10, l11};
    }
}

// ---------------------------------------------------------------------------
// Host launch (graph-capturable: kernels only)
// ---------------------------------------------------------------------------
extern "C" void kernel_launch(void* const* d_in, const int* in_sizes, int n_in,
                              void* d_out, int out_size) {
    const float* v   = (const float*)d_in[0];
    const float* k   = (const float*)d_in[1];
    const float* q   = (const float*)d_in[2];
    const float* lng = (const float*)d_in[4];
    const float* lnb = (const float*)d_in[5];
    const float* Wq  = (const float*)d_in[6];
    const float* Wk  = (const float*)d_in[7];
    const float* Wv  = (const float*)d_in[8];
    const float* Wp  = (const float*)d_in[9];
    const float* bp  = (const float*)d_in[10];
    float* out = (float*)d_out;

    cudaFuncSetAttribute(gemm_qkv_kernel,
                         cudaFuncAttributeMaxDynamicSharedMemorySize, GH_SMEM);
    cudaFuncSetAttribute(gemm_out_kernel,
                         cudaFuncAttributeMaxDynamicSharedMemorySize, GH_SMEM);
    cudaFuncSetAttribute(attn2_kernel,
                         cudaFuncAttributeMaxDynamicSharedMemorySize, AT2_SMEM);

    reorder_kernel<<<(Dd * Dd) / 256, 256>>>(Wq, Wk, Wv, Wp);
    ln_kernel<<<dim3(MM, 3), 256>>>(v, k, q, lng, lnb);
    gemm_qkv_kernel<<<dim3(Dd / 128, MM / 128, 3), 256, GH_SMEM>>>();
    vt_kernel<<<dim3(Ss / 64, Bb * Hh), 256>>>();
    attn2_kernel<<<dim3(Ss / 128, Bb * Hh), 256, AT2_SMEM>>>();
    gemm_out_kernel<<<dim3(Dd / 128, MM / 128), 256, GH_SMEM>>>(out, bp);
}

// round 15
// speedup vs baseline: 5.1137x; 1.1870x over previous
#include <cuda_runtime.h>
#include <cuda_fp16.h>
#include <cstdint>
#include <math.h>

// Problem constants
#define Bb  4
#define Ss  2048
#define Dd  1024
#define Hh  16
#define HSs 64
#define MM  (Bb*Ss)   // 8192 rows

// ---------------------------------------------------------------------------
// PTX helpers (baseline PTX only — harness emits compute_103, no 'a' features)
// ---------------------------------------------------------------------------
__device__ __forceinline__ uint32_t smem_u32(const void* p) {
    uint32_t a;
    asm("{ .reg .u64 t; cvta.to.shared.u64 t, %1; cvt.u32.u64 %0, t; }"
        : "=r"(a) : "l"(p));
    return a;
}

#define CP_ASYNC16(smem_addr, gptr) \
    asm volatile("cp.async.cg.shared.global [%0], [%1], 16;" \
                 :: "r"((uint32_t)(smem_addr)), "l"(gptr) : "memory")
#define CP_COMMIT() asm volatile("cp.async.commit_group;" ::: "memory")
#define CP_WAIT(n)  asm volatile("cp.async.wait_group %0;" :: "n"(n) : "memory")

__device__ __forceinline__ void ldsm4(uint32_t r[4], uint32_t addr) {
    asm volatile("ldmatrix.sync.aligned.m8n8.x4.shared.b16 {%0,%1,%2,%3}, [%4];"
                 : "=r"(r[0]), "=r"(r[1]), "=r"(r[2]), "=r"(r[3]) : "r"(addr));
}

__device__ __forceinline__ void mma16816h(float c[4], const uint32_t a[4],
                                          uint32_t b0, uint32_t b1) {
    asm volatile(
        "mma.sync.aligned.m16n8k16.row.col.f32.f16.f16.f32 "
        "{%0,%1,%2,%3}, {%4,%5,%6,%7}, {%8,%9}, {%0,%1,%2,%3};"
        : "+f"(c[0]), "+f"(c[1]), "+f"(c[2]), "+f"(c[3])
        : "r"(a[0]), "r"(a[1]), "r"(a[2]), "r"(a[3]), "r"(b0), "r"(b1));
}

__device__ __forceinline__ uint32_t packh2(float a, float b) {
    __half2 h = __floats2half2_rn(a, b);
    return *(uint32_t*)&h;
}

__device__ __forceinline__ void h_split(float x, __half& h, __half& l) {
    h = __float2half(x);
    l = __float2half(x - __half2float(h));
}

// ---------------------------------------------------------------------------
// Device scratch (all fp16)
// ---------------------------------------------------------------------------
__device__ __half g_lnv16[MM*Dd];          // plain fp16 LN outputs (QKV GEMM A)
__device__ __half g_lnk16[MM*Dd];
__device__ __half g_lnq16[MM*Dd];
__device__ __half g_q16[MM*Dd];            // Q * D^-0.5
__device__ __half g_k16[MM*Dd];
__device__ __half g_v16[MM*Dd];
__device__ __half g_vt16[Bb*Hh*HSs*Ss];    // [(b*16+h)*64+e][s]
__device__ __half g_attnhi[MM*Dd];
__device__ __half g_attnlo[MM*Dd];
__device__ __half g_Wq16[Dd*Dd];           // [N,K]
__device__ __half g_Wk16[Dd*Dd];
__device__ __half g_Wv16[Dd*Dd];
__device__ __half g_Wp16[Dd*Dd];

// ---------------------------------------------------------------------------
// Weight reorder to [N,K] fp16. Wx[h,d,e] -> W[n=h*64+e][k=d]; Wp already [N,K].
// ---------------------------------------------------------------------------
__global__ void reorder_kernel(const float* __restrict__ Wq,
                               const float* __restrict__ Wk,
                               const float* __restrict__ Wv,
                               const float* __restrict__ Wp) {
    int idx = blockIdx.x * 256 + threadIdx.x;   // n*1024 + k
    int n = idx >> 10;
    int k = idx & 1023;
    int h = n >> 6;
    int e = n & 63;
    int src = h * (Dd * HSs) + k * HSs + e;
    g_Wq16[idx] = __float2half(Wq[src]);
    g_Wk16[idx] = __float2half(Wk[src]);
    g_Wv16[idx] = __float2half(Wv[src]);
    g_Wp16[idx] = __float2half(Wp[idx]);
}

// ---------------------------------------------------------------------------
// Fused layernorm for v,k,q  (grid: (MM, 3), 256 threads) -> plain fp16
// ---------------------------------------------------------------------------
__global__ __launch_bounds__(256) void ln_kernel(const float* __restrict__ v,
                                                 const float* __restrict__ k,
                                                 const float* __restrict__ q,
                                                 const float* __restrict__ g,
                                                 const float* __restrict__ b) {
    int row   = blockIdx.x;
    int which = blockIdx.y;
    const float* x;
    __half* y;
    if (which == 0)      { x = v; y = g_lnv16; }
    else if (which == 1) { x = k; y = g_lnk16; }
    else                 { x = q; y = g_lnq16; }
    x += (size_t)row * Dd;
    y += (size_t)row * Dd;

    int t = threadIdx.x;
    float4 xv = ((const float4*)x)[t];
    float s1 = xv.x + xv.y + xv.z + xv.w;
    float s2 = xv.x*xv.x + xv.y*xv.y + xv.z*xv.z + xv.w*xv.w;
    #pragma unroll
    for (int off = 16; off; off >>= 1) {
        s1 += __shfl_xor_sync(0xffffffffu, s1, off);
        s2 += __shfl_xor_sync(0xffffffffu, s2, off);
    }
    __shared__ float w1[8], w2[8];
    __shared__ float smu, srs;
    int wid = t >> 5, lid = t & 31;
    if (lid == 0) { w1[wid] = s1; w2[wid] = s2; }
    __syncthreads();
    if (t == 0) {
        float t1 = 0.f, t2 = 0.f;
        #pragma unroll
        for (int i = 0; i < 8; i++) { t1 += w1[i]; t2 += w2[i]; }
        float mu  = t1 * (1.0f / Dd);
        float var = t2 * (1.0f / Dd) - mu * mu;
        smu = mu;
        srs = rsqrtf(var + 1e-5f);
    }
    __syncthreads();
    float mu = smu, rs = srs;
    float4 gv = ((const float4*)g)[t];
    float4 bv = ((const float4*)b)[t];
    float y0 = (xv.x - mu) * rs * gv.x + bv.x;
    float y1 = (xv.y - mu) * rs * gv.y + bv.y;
    float y2 = (xv.z - mu) * rs * gv.z + bv.z;
    float y3 = (xv.w - mu) * rs * gv.w + bv.w;
    __half2* y2p = (__half2*)y;
    y2p[2*t]   = __floats2half2_rn(y0, y1);
    y2p[2*t+1] = __floats2half2_rn(y2, y3);
}

// ---------------------------------------------------------------------------
// mma.sync GEMM core, templated on A-compensation:
//   LO=true : C = (A + Alo) x B^T  (stage AH|AL|B = 24KB)
//   LO=false: C = A x B^T          (stage A|B     = 16KB)
// CTA tile 128x128, BK=32, 8 warps (2x4), 3-stage cp.async, 1 barrier/chunk.
// Swizzle: 64B rows, chunk ^ ((row>>1)&3).
// ---------------------------------------------------------------------------
#define GH_STAGE_LO 24576
#define GH_STAGE_PL 16384
#define GH_SMEM_LO  (3 * GH_STAGE_LO)   // 73728
#define GH_SMEM_PL  (3 * GH_STAGE_PL)   // 49152

template<bool LO>
__device__ __forceinline__ void gh_load(const __half* A, const __half* Alo,
                                        const __half* Bm,
                                        int m0, int n0, int k0,
                                        uint32_t stage_base, int tid) {
    const int ITER = LO ? 6 : 4;
    #pragma unroll
    for (int i = 0; i < ITER; i++) {
        int gid = tid + i * 256;
        int arr = gid >> 9;               // LO: 0:A 1:Alo 2:B  | plain: 0:A 1:B
        int idx = gid & 511;
        int row = idx >> 2;               // 0..127
        int c   = idx & 3;                // 16B chunk in 64B row
        uint32_t dst = stage_base + (uint32_t)arr * 8192u
                     + (uint32_t)row * 64u + (uint32_t)((c ^ ((row >> 1) & 3)) << 4);
        const __half* p;
        int g0;
        if (LO) { p = (arr == 0) ? A : ((arr == 1) ? Alo : Bm); g0 = (arr == 2) ? n0 : m0; }
        else    { p = (arr == 0) ? A : Bm;                      g0 = (arr == 1) ? n0 : m0; }
        CP_ASYNC16(dst, p + (size_t)(g0 + row) * Dd + k0 + c * 8);
    }
    CP_COMMIT();
}

template<bool LO>
__device__ __forceinline__ void gh_mainloop(float acc[4][4][4],
                                            const __half* A, const __half* Alo,
                                            const __half* Bm,
                                            int m0, int n0,
                                            uint32_t sb, int tid) {
    const uint32_t STAGE = LO ? GH_STAGE_LO : GH_STAGE_PL;
    const uint32_t BOFF  = LO ? 16384u : 8192u;
    int wid  = tid >> 5;
    int lane = tid & 31;
    int wm = wid & 1;
    int wn = wid >> 1;
    int ti = lane >> 3, lr = lane & 7;

    const int NC = Dd / 32;   // 32 chunks
    gh_load<LO>(A, Alo, Bm, m0, n0, 0, sb, tid);
    gh_load<LO>(A, Alo, Bm, m0, n0, 32, sb + STAGE, tid);

    int st = 0;
    int stN = 2;
    for (int c = 0; c < NC; c++) {
        if (c + 1 < NC) { CP_WAIT(1); } else { CP_WAIT(0); }
        __syncthreads();
        if (c + 2 < NC)
            gh_load<LO>(A, Alo, Bm, m0, n0, (c + 2) * 32,
                        sb + (uint32_t)stN * STAGE, tid);
        uint32_t sBase = sb + (uint32_t)st * STAGE;
        st  = (st  == 2) ? 0 : st + 1;
        stN = (stN == 2) ? 0 : stN + 1;

        #pragma unroll
        for (int kk = 0; kk < 32; kk += 16) {
            uint32_t aH[4][4], aL[4][4], bF[2][4];
            #pragma unroll
            for (int mt = 0; mt < 4; mt++) {
                int row = wm * 64 + mt * 16 + lr + (ti & 1) * 8;
                int ch  = (kk >> 3) + (ti >> 1);
                uint32_t ad = sBase + (uint32_t)row * 64u
                            + (uint32_t)((ch ^ ((row >> 1) & 3)) << 4);
                ldsm4(aH[mt], ad);
                if (LO) ldsm4(aL[mt], ad + 8192);
            }
            #pragma unroll
            for (int ng = 0; ng < 2; ng++) {
                int row = wn * 32 + ng * 16 + lr + (ti >> 1) * 8;
                int ch  = (kk >> 3) + (ti & 1);
                uint32_t bd = sBase + BOFF + (uint32_t)row * 64u
                            + (uint32_t)((ch ^ ((row >> 1) & 3)) << 4);
                ldsm4(bF[ng], bd);
            }
            #pragma unroll
            for (int mt = 0; mt < 4; mt++)
                #pragma unroll
                for (int nt = 0; nt < 4; nt++) {
                    int ng = nt >> 1, hb = (nt & 1) * 2;
                    mma16816h(acc[mt][nt], aH[mt], bF[ng][hb], bF[ng][hb + 1]);
                    if (LO) mma16816h(acc[mt][nt], aL[mt], bF[ng][hb], bF[ng][hb + 1]);
                }
        }
    }
    __syncthreads();
}

// QKV projections batched (plain fp16 A): z=0 Q(*D^-0.5), z=1 K, z=2 V
__global__ __launch_bounds__(256, 1) void gemm_qkv_kernel() {
    extern __shared__ char smem[];
    uint32_t sb = smem_u32(smem);
    int tid = threadIdx.x;
    int z = blockIdx.z;
    int m0 = blockIdx.y * 128;
    int n0 = blockIdx.x * 128;

    const __half *Am, *Bm;
    __half* dst;
    float sc;
    if (z == 0)      { Am = g_lnq16; Bm = g_Wq16; dst = g_q16; sc = 0.03125f; }
    else if (z == 1) { Am = g_lnk16; Bm = g_Wk16; dst = g_k16; sc = 1.0f; }
    else             { Am = g_lnv16; Bm = g_Wv16; dst = g_v16; sc = 1.0f; }

    float acc[4][4][4];
    #pragma unroll
    for (int i = 0; i < 4; i++)
        #pragma unroll
        for (int j = 0; j < 4; j++)
            #pragma unroll
            for (int r = 0; r < 4; r++) acc[i][j][r] = 0.f;

    gh_mainloop<false>(acc, Am, nullptr, Bm, m0, n0, sb, tid);

    int wid = tid >> 5, lane = tid & 31;
    int wm = wid & 1, wn = wid >> 1;
    #pragma unroll
    for (int mt = 0; mt < 4; mt++) {
        #pragma unroll
        for (int nt = 0; nt < 4; nt++) {
            int row = m0 + wm * 64 + mt * 16 + (lane >> 2);
            int col = n0 + wn * 32 + nt * 8 + (lane & 3) * 2;
            *(uint32_t*)(dst + (size_t)row * Dd + col) =
                packh2(acc[mt][nt][0] * sc, acc[mt][nt][1] * sc);
            *(uint32_t*)(dst + (size_t)(row + 8) * Dd + col) =
                packh2(acc[mt][nt][2] * sc, acc[mt][nt][3] * sc);
        }
    }
}

// Output projection (fp16x2 A = attn hi/lo): C = fp32 out + bias
__global__ __launch_bounds__(256, 1) void gemm_out_kernel(float* __restrict__ C,
                                                          const float* __restrict__ bias) {
    extern __shared__ char smem[];
    uint32_t sb = smem_u32(smem);
    int tid = threadIdx.x;
    int m0 = blockIdx.y * 128;
    int n0 = blockIdx.x * 128;

    float acc[4][4][4];
    #pragma unroll
    for (int i = 0; i < 4; i++)
        #pragma unroll
        for (int j = 0; j < 4; j++)
            #pragma unroll
            for (int r = 0; r < 4; r++) acc[i][j][r] = 0.f;

    gh_mainloop<true>(acc, g_attnhi, g_attnlo, g_Wp16, m0, n0, sb, tid);

    int wid = tid >> 5, lane = tid & 31;
    int wm = wid & 1, wn = wid >> 1;
    #pragma unroll
    for (int mt = 0; mt < 4; mt++) {
        #pragma unroll
        for (int nt = 0; nt < 4; nt++) {
            int row = m0 + wm * 64 + mt * 16 + (lane >> 2);
            int col = n0 + wn * 32 + nt * 8 + (lane & 3) * 2;
            float b0 = bias[col], b1 = bias[col + 1];
            *(float2*)(C + (size_t)row * Dd + col) =
                make_float2(acc[mt][nt][0] + b0, acc[mt][nt][1] + b1);
            *(float2*)(C + (size_t)(row + 8) * Dd + col) =
                make_float2(acc[mt][nt][2] + b0, acc[mt][nt][3] + b1);
        }
    }
}

// ---------------------------------------------------------------------------
// V transpose: g_v16 [token][h*64+e] -> g_vt16 [(b*16+h)*64+e][s]
// ---------------------------------------------------------------------------
__global__ __launch_bounds__(256) void vt_kernel() {
    __shared__ __half ts[64][66];
    int s0 = blockIdx.x * 64;
    int bh = blockIdx.y;
    int b  = bh >> 4;
    int h  = bh & 15;
    int tid = threadIdx.x;
    #pragma unroll
    for (int i = 0; i < 16; i++) {
        int idx = tid + i * 256;
        int r = idx >> 6, e = idx & 63;
        ts[r][e] = g_v16[(size_t)(b * Ss + s0 + r) * Dd + h * HSs + e];
    }
    __syncthreads();
    #pragma unroll
    for (int i = 0; i < 16; i++) {
        int idx = tid + i * 256;
        int e = idx >> 6, t = idx & 63;
        g_vt16[((size_t)bh * HSs + e) * Ss + s0 + t] = ts[t][e];
    }
}

// ---------------------------------------------------------------------------
// Flash attention v2: fp16 mma.sync, causal, double-buffered K/V.
// BM=128, BN=64, 8 warps. smem: Q 16K | K0 8K | V0 8K | K1 8K | V1 8K = 48K
// grid: (S/128, B*H)
// ---------------------------------------------------------------------------
#define AT_Q  0
#define AT_KV 16384
#define AT2_SMEM 49152

__device__ __forceinline__ void at_load_kv(uint32_t sb, int s, int b, int bh,
                                           int k0, int tid) {
    uint32_t base = sb + AT_KV + (uint32_t)s * 16384u;
    #pragma unroll
    for (int i = 0; i < 2; i++) {
        int idx = tid + i * 256;
        int row = idx >> 3, c = idx & 7;
        uint32_t sw = (uint32_t)((c ^ (row & 7)) << 4);
        CP_ASYNC16(base + (uint32_t)row * 128u + sw,
                   g_k16 + (size_t)(b * Ss + k0 + row) * Dd + (bh & 15) * HSs + c * 8);
        CP_ASYNC16(base + 8192u + (uint32_t)row * 128u + sw,
                   g_vt16 + ((size_t)bh * HSs + row) * Ss + k0 + c * 8);
    }
    CP_COMMIT();
}

__global__ __launch_bounds__(256, 1) void attn2_kernel() {
    extern __shared__ char smem[];
    uint32_t sb = smem_u32(smem);
    int qb = blockIdx.x;
    int bh = blockIdx.y;
    int b  = bh >> 4;
    int h  = bh & 15;
    int q0 = qb * 128;

    int tid  = threadIdx.x;
    int wid  = tid >> 5;
    int lane = tid & 31;
    int lr = lane & 7, ti = lane >> 3;

    // Load Q tile (128 x 64 fp16)
    #pragma unroll
    for (int i = 0; i < 4; i++) {
        int idx = tid + i * 256;
        int row = idx >> 3, c = idx & 7;
        uint32_t dst = sb + AT_Q + (uint32_t)row * 128u + (uint32_t)((c ^ (row & 7)) << 4);
        CP_ASYNC16(dst, g_q16 + (size_t)(b * Ss + q0 + row) * Dd + h * HSs + c * 8);
    }
    CP_COMMIT();
    at_load_kv(sb, 0, b, bh, 0, tid);

    float m0 = -1e30f, m1 = -1e30f, l0 = 0.f, l1 = 0.f;
    float O[8][4];
    #pragma unroll
    for (int f = 0; f < 8; f++)
        #pragma unroll
        for (int r = 0; r < 4; r++) O[f][r] = 0.f;

    int NB = 2 * qb + 2;
    for (int kb = 0; kb < NB; kb++) {
        int s = kb & 1;
        int k0 = kb * 64;
        CP_WAIT(0);
        __syncthreads();
        if (kb + 1 < NB) at_load_kv(sb, s ^ 1, b, bh, (kb + 1) * 64, tid);

        uint32_t sK = sb + AT_KV + (uint32_t)s * 16384u;
        uint32_t sV = sK + 8192u;

        // S = Q K^T
        uint32_t aQ[4][4];
        #pragma unroll
        for (int ks = 0; ks < 4; ks++) {
            int row = wid * 16 + lr + (ti & 1) * 8;
            int ch  = 2 * ks + (ti >> 1);
            ldsm4(aQ[ks], sb + AT_Q + (uint32_t)row * 128u
                          + (uint32_t)((ch ^ (row & 7)) << 4));
        }
        float S[8][4];
        #pragma unroll
        for (int f = 0; f < 8; f++)
            #pragma unroll
            for (int r = 0; r < 4; r++) S[f][r] = 0.f;

        #pragma unroll
        for (int nt = 0; nt < 4; nt++) {
            int krow = nt * 16 + lr + (ti >> 1) * 8;
            #pragma unroll
            for (int ks = 0; ks < 4; ks++) {
                int ch = 2 * ks + (ti & 1);
                uint32_t bK[4];
                ldsm4(bK, sK + (uint32_t)krow * 128u
                          + (uint32_t)((ch ^ (krow & 7)) << 4));
                mma16816h(S[2 * nt],     aQ[ks], bK[0], bK[1]);
                mma16816h(S[2 * nt + 1], aQ[ks], bK[2], bK[3]);
            }
        }

        // causal mask (diagonal band only)
        if (kb >= 2 * qb) {
            int r0 = q0 + wid * 16 + (lane >> 2);
            #pragma unroll
            for (int f = 0; f < 8; f++) {
                int kg = k0 + f * 8 + 2 * (lane & 3);
                if (kg     > r0)     S[f][0] = -1e30f;
                if (kg + 1 > r0)     S[f][1] = -1e30f;
                if (kg     > r0 + 8) S[f][2] = -1e30f;
                if (kg + 1 > r0 + 8) S[f][3] = -1e30f;
            }
        }

        // online softmax
        float mx0 = -1e30f, mx1 = -1e30f;
        #pragma unroll
        for (int f = 0; f < 8; f++) {
            mx0 = fmaxf(mx0, fmaxf(S[f][0], S[f][1]));
            mx1 = fmaxf(mx1, fmaxf(S[f][2], S[f][3]));
        }
        mx0 = fmaxf(mx0, __shfl_xor_sync(0xffffffffu, mx0, 1));
        mx0 = fmaxf(mx0, __shfl_xor_sync(0xffffffffu, mx0, 2));
        mx1 = fmaxf(mx1, __shfl_xor_sync(0xffffffffu, mx1, 1));
        mx1 = fmaxf(mx1, __shfl_xor_sync(0xffffffffu, mx1, 2));
        float mn0 = fmaxf(m0, mx0), mn1 = fmaxf(m1, mx1);
        float al0 = __expf(m0 - mn0), al1 = __expf(m1 - mn1);
        float rs0 = 0.f, rs1 = 0.f;
        #pragma unroll
        for (int f = 0; f < 8; f++) {
            S[f][0] = __expf(S[f][0] - mn0);
            S[f][1] = __expf(S[f][1] - mn0);
            S[f][2] = __expf(S[f][2] - mn1);
            S[f][3] = __expf(S[f][3] - mn1);
            rs0 += S[f][0] + S[f][1];
            rs1 += S[f][2] + S[f][3];
        }
        rs0 += __shfl_xor_sync(0xffffffffu, rs0, 1);
        rs0 += __shfl_xor_sync(0xffffffffu, rs0, 2);
        rs1 += __shfl_xor_sync(0xffffffffu, rs1, 1);
        rs1 += __shfl_xor_sync(0xffffffffu, rs1, 2);
        l0 = l0 * al0 + rs0;
        l1 = l1 * al1 + rs1;
        m0 = mn0; m1 = mn1;
        #pragma unroll
        for (int f = 0; f < 8; f++) {
            O[f][0] *= al0; O[f][1] *= al0;
            O[f][2] *= al1; O[f][3] *= al1;
        }

        // P fragments (C-frag -> A-frag identity)
        uint32_t aP[4][4];
        #pragma unroll
        for (int f2 = 0; f2 < 4; f2++) {
            aP[f2][0] = packh2(S[2 * f2][0],     S[2 * f2][1]);
            aP[f2][1] = packh2(S[2 * f2][2],     S[2 * f2][3]);
            aP[f2][2] = packh2(S[2 * f2 + 1][0], S[2 * f2 + 1][1]);
            aP[f2][3] = packh2(S[2 * f2 + 1][2], S[2 * f2 + 1][3]);
        }

        // O += P V
        #pragma unroll
        for (int nt = 0; nt < 4; nt++) {
            int vrow = nt * 16 + lr + (ti >> 1) * 8;
            #pragma unroll
            for (int f2 = 0; f2 < 4; f2++) {
                int ch = 2 * f2 + (ti & 1);
                uint32_t bV[4];
                ldsm4(bV, sV + (uint32_t)vrow * 128u
                          + (uint32_t)((ch ^ (vrow & 7)) << 4));
                mma16816h(O[2 * nt],     aP[f2], bV[0], bV[1]);
                mma16816h(O[2 * nt + 1], aP[f2], bV[2], bV[3]);
            }
        }
    }

    // Epilogue: normalize + fp16 hi/lo split
    float inv0 = 1.0f / l0, inv1 = 1.0f / l1;
    int row0 = q0 + wid * 16 + (lane >> 2);
    #pragma unroll
    for (int f = 0; f < 8; f++) {
        int col = h * HSs + f * 8 + 2 * (lane & 3);
        float v00 = O[f][0] * inv0, v01 = O[f][1] * inv0;
        float v10 = O[f][2] * inv1, v11 = O[f][3] * inv1;
        __half h00, l00, h01, l01, h10, l10, h11, l11;
        h_split(v00, h00, l00); h_split(v01, h01, l01);
        h_split(v10, h10, l10); h_split(v11, h11, l11);
        size_t o0 = (size_t)(b * Ss + row0) * Dd + col;
        size_t o1 = (size_t)(b * Ss + row0 + 8) * Dd + col;
        *(__half2*)(g_attnhi + o0) = __half2{h00, h01};
        *(__half2*)(g_attnlo + o0) = __half2{l00, l01};
        *(__half2*)(g_attnhi + o1) = __half2{h10, h11};
        *(__half2*)(g_attnlo + o1) = __half2{l10, l11};
    }
}

// ---------------------------------------------------------------------------
// Host launch (graph-capturable: kernels only)
// ---------------------------------------------------------------------------
extern "C" void kernel_launch(void* const* d_in, const int* in_sizes, int n_in,
                              void* d_out, int out_size) {
    const float* v   = (const float*)d_in[0];
    const float* k   = (const float*)d_in[1];
    const float* q   = (const float*)d_in[2];
    const float* lng = (const float*)d_in[4];
    const float* lnb = (const float*)d_in[5];
    const float* Wq  = (const float*)d_in[6];
    const float* Wk  = (const float*)d_in[7];
    const float* Wv  = (const float*)d_in[8];
    const float* Wp  = (const float*)d_in[9];
    const float* bp  = (const float*)d_in[10];
    float* out = (float*)d_out;

    cudaFuncSetAttribute(gemm_qkv_kernel,
                         cudaFuncAttributeMaxDynamicSharedMemorySize, GH_SMEM_PL);
    cudaFuncSetAttribute(gemm_out_kernel,
                         cudaFuncAttributeMaxDynamicSharedMemorySize, GH_SMEM_LO);
    cudaFuncSetAttribute(attn2_kernel,
                         cudaFuncAttributeMaxDynamicSharedMemorySize, AT2_SMEM);

    reorder_kernel<<<(Dd * Dd) / 256, 256>>>(Wq, Wk, Wv, Wp);
    ln_kernel<<<dim3(MM, 3), 256>>>(v, k, q, lng, lnb);
    gemm_qkv_kernel<<<dim3(Dd / 128, MM / 128, 3), 256, GH_SMEM_PL>>>();
    vt_kernel<<<dim3(Ss / 64, Bb * Hh), 256>>>();
    attn2_kernel<<<dim3(Ss / 128, Bb * Hh), 256, AT2_SMEM>>>();
    gemm_out_kernel<<<dim3(Dd / 128, MM / 128), 256, GH_SMEM_LO>>>(out, bp);
}